// round 4
// baseline (speedup 1.0000x reference)
#include <cuda_runtime.h>
#include <math.h>
#include <stdint.h>

// ---------------- problem dims ----------------
#define NB    4096
#define NIN   8192
#define NEMB  1024
#define NK    4096
#define NCD   256
#define NFLAT 16384
#define OUT_PERP_OFF ((size_t)1 + (size_t)NB * (size_t)NIN)

#define EPI_BN_RELU 0
#define EPI_BIAS    1
#define EPI_RES     2
#define EPI_SIG     3

// ---------------- scratch (device globals) ----------------
__device__ float g_a   [(size_t)NB * NEMB];
__device__ float g_ar  [(size_t)NB * NEMB];
__device__ float g_b   [(size_t)NB * NEMB];
__device__ float g_br  [(size_t)NB * NEMB];
__device__ float g_z   [(size_t)NB * NEMB];
__device__ float g_cnorm[NK];
__device__ int   g_idx[NFLAT];
__device__ int   g_cnt[NK];
__device__ float g_losspart[NFLAT / 8];

// ---------------- small helpers ----------------
__device__ __forceinline__ uint32_t rtf32_u(float x) {
    uint32_t r;
    asm("cvt.rna.tf32.f32 %0, %1;" : "=r"(r) : "f"(x));
    return r;
}
__device__ __forceinline__ float rtf32(float x) {
    return __uint_as_float(rtf32_u(x));
}
__device__ __forceinline__ void cp16(uint32_t dst, const void* src) {
    asm volatile("cp.async.cg.shared.global [%0], [%1], 16;" :: "r"(dst), "l"(src));
}
__device__ __forceinline__ void cp_commit() {
    asm volatile("cp.async.commit_group;");
}
template<int N>
__device__ __forceinline__ void cp_wait() {
    asm volatile("cp.async.wait_group %0;" :: "n"(N));
}
__device__ __forceinline__ void mma8(float* c, const uint32_t* a, const uint32_t* b) {
    asm volatile(
        "mma.sync.aligned.m16n8k8.row.col.f32.tf32.tf32.f32 "
        "{%0,%1,%2,%3},{%4,%5,%6,%7},{%8,%9},{%0,%1,%2,%3};"
        : "+f"(c[0]), "+f"(c[1]), "+f"(c[2]), "+f"(c[3])
        : "r"(a[0]), "r"(a[1]), "r"(a[2]), "r"(a[3]), "r"(b[0]), "r"(b[1]));
}

// ---------------- tf32 tensor-core GEMM ----------------
// block tile 128x128, BK=32, 8 warps (4x2), warp tile 32x64, m16n8k8.
// 2 CTAs/SM (<=128 regs) for latency hiding.
#define TBM 128
#define TBN 128
#define TBK 32
#define A_STR 36                         // BK + 4 pad (floats)
#define AS_SZ (TBM * A_STR)              // 4608 floats / stage
#define BS_SZ (TBK * TBN)                // 4096 floats / stage
#define GEMM_SMEM ((2 * AS_SZ + 2 * BS_SZ) * 4)   // 69632 B

template<int EPI, bool WRELU, bool CVTA>
__global__ void __launch_bounds__(256, 2)
gemm_tc(const float* __restrict__ A, const float* __restrict__ W,
        const float* __restrict__ bias,
        const float* __restrict__ gamma, const float* __restrict__ beta,
        const float* __restrict__ mean,  const float* __restrict__ var,
        const float* __restrict__ res,
        float* __restrict__ out0, float* __restrict__ out1,
        int M, int N, int K)
{
    extern __shared__ float smem[];
    float* As = smem;                    // 2 stages
    float* Bs = smem + 2 * AS_SZ;
    const uint32_t s_as = (uint32_t)__cvta_generic_to_shared(As);
    const uint32_t s_bs = (uint32_t)__cvta_generic_to_shared(Bs);

    const int tid  = threadIdx.x;
    const int lane = tid & 31;
    const int warp = tid >> 5;
    const int wm   = warp >> 1;          // 0..3  (32 rows each)
    const int wn   = warp & 1;           // 0..1  (64 cols each)
    const int row0 = blockIdx.y * TBM;
    const int col0 = blockIdx.x * TBN;
    const int l4   = lane >> 2;          // 0..7
    const int lm   = lane & 3;           // 0..3

    float acc[2][8][4];
#pragma unroll
    for (int mt = 0; mt < 2; mt++)
#pragma unroll
        for (int nt = 0; nt < 8; nt++)
#pragma unroll
            for (int q = 0; q < 4; q++) acc[mt][nt][q] = 0.f;

    const int iters = K / TBK;

    auto loadA = [&](int s, int k0) {
#pragma unroll
        for (int i = 0; i < 4; i++) {
            int idx = i * 256 + tid;
            int r = idx >> 3, kc = (idx & 7) << 2;
            cp16(s_as + (uint32_t)(s * AS_SZ + r * A_STR + kc) * 4,
                 A + (size_t)(row0 + r) * K + k0 + kc);
        }
    };
    auto loadB = [&](int s, int k0) {
#pragma unroll
        for (int i = 0; i < 4; i++) {
            int idx = i * 256 + tid;
            int k = idx >> 5, nc = (idx & 31) << 2;
            int nsw = nc ^ ((k & 3) << 3);
            cp16(s_bs + (uint32_t)(s * BS_SZ + k * TBN + nsw) * 4,
                 W + (size_t)(k0 + k) * N + col0 + nc);
        }
    };

    loadA(0, 0); loadB(0, 0); cp_commit();

    int s = 0;
    for (int it = 0; it < iters; it++) {
        if (it + 1 < iters) {
            loadA(s ^ 1, (it + 1) * TBK);
            loadB(s ^ 1, (it + 1) * TBK);
            cp_commit();
            cp_wait<1>();
        } else {
            cp_wait<0>();
        }
        __syncthreads();

        const float* as = As + s * AS_SZ;
        const float* bs = Bs + s * BS_SZ;
#pragma unroll
        for (int kk = 0; kk < TBK; kk += 8) {
            uint32_t af[2][4], bf[8][2];
#pragma unroll
            for (int mt = 0; mt < 2; mt++) {
                int r = wm * 32 + mt * 16 + l4;
                if (CVTA) {
                    af[mt][0] = rtf32_u(as[r * A_STR + kk + lm]);
                    af[mt][1] = rtf32_u(as[(r + 8) * A_STR + kk + lm]);
                    af[mt][2] = rtf32_u(as[r * A_STR + kk + 4 + lm]);
                    af[mt][3] = rtf32_u(as[(r + 8) * A_STR + kk + 4 + lm]);
                } else {
                    af[mt][0] = __float_as_uint(as[r * A_STR + kk + lm]);
                    af[mt][1] = __float_as_uint(as[(r + 8) * A_STR + kk + lm]);
                    af[mt][2] = __float_as_uint(as[r * A_STR + kk + 4 + lm]);
                    af[mt][3] = __float_as_uint(as[(r + 8) * A_STR + kk + 4 + lm]);
                }
            }
#pragma unroll
            for (int nt = 0; nt < 8; nt++) {
                int c   = wn * 64 + nt * 8 + l4;
                int csw = c ^ (lm << 3);
                bf[nt][0] = rtf32_u(bs[(kk + lm) * TBN + csw]);
                bf[nt][1] = rtf32_u(bs[(kk + 4 + lm) * TBN + csw]);
            }
#pragma unroll
            for (int mt = 0; mt < 2; mt++)
#pragma unroll
                for (int nt = 0; nt < 8; nt++)
                    mma8(acc[mt][nt], af[mt], bf[nt]);
        }
        __syncthreads();
        s ^= 1;
    }

    // ---- epilogue ----
#pragma unroll
    for (int nt = 0; nt < 8; nt++) {
        int c = col0 + wn * 64 + nt * 8 + (lm << 1);
        float b0 = bias[c], b1 = bias[c + 1];
        float g0 = 0.f, g1 = 0.f, be0 = 0.f, be1 = 0.f, m0 = 0.f, m1 = 0.f;
        if (EPI == EPI_BN_RELU || EPI == EPI_RES) {
            g0 = gamma[c]     * rsqrtf(var[c]     + 1e-5f);
            g1 = gamma[c + 1] * rsqrtf(var[c + 1] + 1e-5f);
            be0 = beta[c]; be1 = beta[c + 1];
            m0 = mean[c]; m1 = mean[c + 1];
        }
#pragma unroll
        for (int mt = 0; mt < 2; mt++) {
#pragma unroll
            for (int h = 0; h < 2; h++) {
                int r = row0 + wm * 32 + mt * 16 + l4 + h * 8;
                size_t off = (size_t)r * N + c;
                float x0 = acc[mt][nt][h * 2 + 0] + b0;
                float x1 = acc[mt][nt][h * 2 + 1] + b1;
                if (EPI == EPI_BN_RELU) {
                    x0 = fmaxf((x0 - m0) * g0 + be0, 0.f);
                    x1 = fmaxf((x1 - m1) * g1 + be1, 0.f);
                } else if (EPI == EPI_RES) {
                    float2 rv = *(const float2*)(res + off);
                    x0 = (x0 - m0) * g0 + be0 + rv.x;
                    x1 = (x1 - m1) * g1 + be1 + rv.y;
                } else if (EPI == EPI_SIG) {
                    out0[off]     = 1.f / (1.f + expf(-x0));
                    out0[off + 1] = 1.f / (1.f + expf(-x1));
                    continue;
                }
                float r0 = rtf32(x0), r1 = rtf32(x1);
                float2 v; v.x = r0; v.y = r1;
                *(float2*)(out0 + off) = v;
                if (WRELU) {
                    float2 w; w.x = fmaxf(r0, 0.f); w.y = fmaxf(r1, 0.f);
                    *(float2*)(out1 + off) = w;
                }
            }
        }
    }
}

// ---------------- VQ: tf32 mma distances + fused argmin ----------------
// 64 rows/CTA (256 CTAs), codes in tiles of 256, K=256. 8 warps (2x4), 32x64.
#define VAS_SZ (64 * A_STR)              // 2304 floats / stage
#define VB_STR 36
#define VBS_SZ (256 * VB_STR)            // 9216 floats / stage
#define VQ_SMEM ((2 * VAS_SZ + 2 * VBS_SZ) * 4)   // 92160 B

__global__ void __launch_bounds__(256, 2)
vq_tc(const float* __restrict__ Z, const float* __restrict__ CB)
{
    extern __shared__ float smem[];
    float* As = smem;
    float* Bs = smem + 2 * VAS_SZ;
    const uint32_t s_as = (uint32_t)__cvta_generic_to_shared(As);
    const uint32_t s_bs = (uint32_t)__cvta_generic_to_shared(Bs);
    __shared__ float sv[64][4];
    __shared__ int   si[64][4];

    const int tid  = threadIdx.x;
    const int lane = tid & 31;
    const int warp = tid >> 5;
    const int wm   = warp >> 2;          // 0..1 (32 rows)
    const int wn   = warp & 3;           // 0..3 (64 codes)
    const int row0 = blockIdx.x * 64;
    const int l4   = lane >> 2;
    const int lm   = lane & 3;

    float minv[2][2];
    int   mini[2][2];
#pragma unroll
    for (int mt = 0; mt < 2; mt++)
#pragma unroll
        for (int h = 0; h < 2; h++) { minv[mt][h] = 3.4e38f; mini[mt][h] = 0; }

    auto loadA = [&](int s, int k0) {
#pragma unroll
        for (int i = 0; i < 2; i++) {
            int idx = i * 256 + tid;
            int r = idx >> 3, kc = (idx & 7) << 2;
            cp16(s_as + (uint32_t)(s * VAS_SZ + r * A_STR + kc) * 4,
                 Z + (size_t)(row0 + r) * NCD + k0 + kc);
        }
    };

    for (int ct = 0; ct < NK; ct += 256) {
        float acc[2][8][4];
#pragma unroll
        for (int mt = 0; mt < 2; mt++)
#pragma unroll
            for (int nt = 0; nt < 8; nt++)
#pragma unroll
                for (int q = 0; q < 4; q++) acc[mt][nt][q] = 0.f;

        auto loadB = [&](int s, int k0) {
#pragma unroll
            for (int i = 0; i < 8; i++) {
                int idx = i * 256 + tid;
                int code = idx >> 3, kc = (idx & 7) << 2;
                cp16(s_bs + (uint32_t)(s * VBS_SZ + code * VB_STR + kc) * 4,
                     CB + (size_t)(ct + code) * NCD + k0 + kc);
            }
        };

        loadA(0, 0); loadB(0, 0); cp_commit();
        int s = 0;
        const int iters = NCD / TBK;      // 8
        for (int it = 0; it < iters; it++) {
            if (it + 1 < iters) {
                loadA(s ^ 1, (it + 1) * TBK);
                loadB(s ^ 1, (it + 1) * TBK);
                cp_commit();
                cp_wait<1>();
            } else {
                cp_wait<0>();
            }
            __syncthreads();

            const float* as = As + s * VAS_SZ;
            const float* bs = Bs + s * VBS_SZ;
#pragma unroll
            for (int kk = 0; kk < TBK; kk += 8) {
                uint32_t af[2][4], bf[8][2];
#pragma unroll
                for (int mt = 0; mt < 2; mt++) {
                    int r = wm * 32 + mt * 16 + l4;
                    af[mt][0] = __float_as_uint(as[r * A_STR + kk + lm]);
                    af[mt][1] = __float_as_uint(as[(r + 8) * A_STR + kk + lm]);
                    af[mt][2] = __float_as_uint(as[r * A_STR + kk + 4 + lm]);
                    af[mt][3] = __float_as_uint(as[(r + 8) * A_STR + kk + 4 + lm]);
                }
#pragma unroll
                for (int nt = 0; nt < 8; nt++) {
                    int cc = wn * 64 + nt * 8 + l4;
                    bf[nt][0] = rtf32_u(bs[cc * VB_STR + kk + lm]);
                    bf[nt][1] = rtf32_u(bs[cc * VB_STR + kk + 4 + lm]);
                }
#pragma unroll
                for (int mt = 0; mt < 2; mt++)
#pragma unroll
                    for (int nt = 0; nt < 8; nt++)
                        mma8(acc[mt][nt], af[mt], bf[nt]);
            }
            __syncthreads();
            s ^= 1;
        }

        // update running per-row argmin:  d = |c|^2 - 2 z.c
#pragma unroll
        for (int nt = 0; nt < 8; nt++) {
            int code = ct + wn * 64 + nt * 8 + (lm << 1);
            float cn0 = g_cnorm[code], cn1 = g_cnorm[code + 1];
#pragma unroll
            for (int mt = 0; mt < 2; mt++)
#pragma unroll
                for (int h = 0; h < 2; h++) {
                    float d0 = cn0 - 2.f * acc[mt][nt][h * 2 + 0];
                    float d1 = cn1 - 2.f * acc[mt][nt][h * 2 + 1];
                    if (d0 < minv[mt][h]) { minv[mt][h] = d0; mini[mt][h] = code; }
                    if (d1 < minv[mt][h]) { minv[mt][h] = d1; mini[mt][h] = code + 1; }
                }
        }
    }

    // quad lanes hold different codes for same rows -> shuffle-reduce
#pragma unroll
    for (int mt = 0; mt < 2; mt++)
#pragma unroll
        for (int h = 0; h < 2; h++) {
            float v = minv[mt][h]; int ix = mini[mt][h];
#pragma unroll
            for (int o = 1; o <= 2; o <<= 1) {
                float vo = __shfl_xor_sync(0xffffffffu, v, o);
                int   io = __shfl_xor_sync(0xffffffffu, ix, o);
                if (vo < v || (vo == v && io < ix)) { v = vo; ix = io; }
            }
            if (lm == 0) {
                int rl = wm * 32 + mt * 16 + l4 + h * 8;
                sv[rl][wn] = v; si[rl][wn] = ix;
            }
        }
    __syncthreads();
    if (tid < 64) {
        float bv = sv[tid][0]; int bi = si[tid][0];
#pragma unroll
        for (int t = 1; t < 4; t++) {
            float v = sv[tid][t]; int k2 = si[tid][t];
            if (v < bv || (v == bv && k2 < bi)) { bv = v; bi = k2; }
        }
        g_idx[row0 + tid] = bi;
        atomicAdd(&g_cnt[bi], 1);
    }
}

// ---------------- misc kernels ----------------
__global__ void zero_cnt_kernel()
{
    int i = blockIdx.x * 256 + threadIdx.x;
    if (i < NK) g_cnt[i] = 0;
}

__global__ __launch_bounds__(256)
void cnorm_kernel(const float* __restrict__ CB)
{
    int warp = threadIdx.x >> 5, lane = threadIdx.x & 31;
    int code = blockIdx.x * 8 + warp;
    const float* c = CB + (size_t)code * NCD;
    float s = 0.f;
#pragma unroll
    for (int e = 0; e < 8; e++) { float v = rtf32(c[e * 32 + lane]); s += v * v; }
#pragma unroll
    for (int o = 16; o > 0; o >>= 1) s += __shfl_xor_sync(0xffffffffu, s, o);
    if (lane == 0) g_cnorm[code] = s;
}

__global__ __launch_bounds__(256)
void gather_loss_kernel(const float* __restrict__ Z, const float* __restrict__ CB,
                        float* __restrict__ HQ, float* __restrict__ HQR)
{
    __shared__ float ws[8];
    int warp = threadIdx.x >> 5, lane = threadIdx.x & 31;
    int row  = blockIdx.x * 8 + warp;
    int id   = g_idx[row];
    const float* q = CB + (size_t)id * NCD;
    const float* z = Z + (size_t)row * NCD;
    float* o   = HQ  + (size_t)row * NCD;
    float* orl = HQR + (size_t)row * NCD;
    float s = 0.f;
#pragma unroll
    for (int e = 0; e < 8; e++) {
        int d = e * 32 + lane;
        float qq = q[d], zz = z[d];
        float qr = rtf32(qq);
        o[d]   = qr;
        orl[d] = fmaxf(qr, 0.f);
        float t = qq - zz;
        s += t * t;
    }
#pragma unroll
    for (int off = 16; off > 0; off >>= 1) s += __shfl_xor_sync(0xffffffffu, s, off);
    if (lane == 0) ws[warp] = s;
    __syncthreads();
    if (threadIdx.x == 0) {
        float t = 0.f;
#pragma unroll
        for (int w = 0; w < 8; w++) t += ws[w];
        g_losspart[blockIdx.x] = t;
    }
}

__global__ __launch_bounds__(256)
void finalize_kernel(float* __restrict__ out)
{
    __shared__ float red[256];
    int tid = threadIdx.x;

    float s = 0.f;
    for (int i = tid; i < NFLAT / 8; i += 256) s += g_losspart[i];
    red[tid] = s; __syncthreads();
    for (int o = 128; o > 0; o >>= 1) { if (tid < o) red[tid] += red[tid + o]; __syncthreads(); }
    float loss = red[0] * (1.25f / ((float)NB * (float)NEMB));
    __syncthreads();

    float e = 0.f;
    for (int i = tid; i < NK; i += 256) {
        float p = (float)g_cnt[i] * (1.0f / (float)NFLAT);
        e += p * logf(p + 1e-10f);
    }
    red[tid] = e; __syncthreads();
    for (int o = 128; o > 0; o >>= 1) { if (tid < o) red[tid] += red[tid + o]; __syncthreads(); }

    if (tid == 0) {
        out[0]            = loss;
        out[OUT_PERP_OFF] = expf(-red[0]);
    }
}

// ---------------- launch ----------------
extern "C" void kernel_launch(void* const* d_in, const int* in_sizes, int n_in,
                              void* d_out, int out_size)
{
    const float* x    = (const float*)d_in[0];
    const float* W1   = (const float*)d_in[1];
    const float* b1   = (const float*)d_in[2];
    const float* bn1g = (const float*)d_in[3];
    const float* bn1b = (const float*)d_in[4];
    const float* bn1m = (const float*)d_in[5];
    const float* bn1v = (const float*)d_in[6];
    const float* W2   = (const float*)d_in[7];
    const float* b2   = (const float*)d_in[8];
    const float* rbW  = (const float*)d_in[9];
    const float* rbb  = (const float*)d_in[10];
    const float* rbg  = (const float*)d_in[11];
    const float* rbbe = (const float*)d_in[12];
    const float* rbm  = (const float*)d_in[13];
    const float* rbv  = (const float*)d_in[14];
    const float* cb   = (const float*)d_in[15];
    const float* decW = (const float*)d_in[16];
    const float* decb = (const float*)d_in[17];
    float* out = (float*)d_out;

    float *ga, *gar, *gb, *gbr, *gz;
    cudaGetSymbolAddress((void**)&ga,  g_a);
    cudaGetSymbolAddress((void**)&gar, g_ar);
    cudaGetSymbolAddress((void**)&gb,  g_b);
    cudaGetSymbolAddress((void**)&gbr, g_br);
    cudaGetSymbolAddress((void**)&gz,  g_z);

    // dynamic smem opt-in (idempotent)
    cudaFuncSetAttribute(gemm_tc<EPI_BN_RELU, false, true >, cudaFuncAttributeMaxDynamicSharedMemorySize, GEMM_SMEM);
    cudaFuncSetAttribute(gemm_tc<EPI_BIAS,    true,  false>, cudaFuncAttributeMaxDynamicSharedMemorySize, GEMM_SMEM);
    cudaFuncSetAttribute(gemm_tc<EPI_RES,     true,  false>, cudaFuncAttributeMaxDynamicSharedMemorySize, GEMM_SMEM);
    cudaFuncSetAttribute(gemm_tc<EPI_RES,     false, false>, cudaFuncAttributeMaxDynamicSharedMemorySize, GEMM_SMEM);
    cudaFuncSetAttribute(gemm_tc<EPI_SIG,     false, false>, cudaFuncAttributeMaxDynamicSharedMemorySize, GEMM_SMEM);
    cudaFuncSetAttribute(vq_tc, cudaFuncAttributeMaxDynamicSharedMemorySize, VQ_SMEM);

    const size_t WS = (size_t)NEMB * NEMB;

    zero_cnt_kernel<<<(NK + 255) / 256, 256>>>();
    cnorm_kernel<<<NK / 8, 256>>>(cb);

    dim3 blk(256);
    dim3 gE(NEMB / TBN, NB / TBM);   // 8 x 32 = 256 CTAs
    dim3 gD(NIN  / TBN, NB / TBM);   // 64 x 32 = 2048 CTAs

    // encoder (x needs cvt on A; activations are pre-rounded at epilogue)
    gemm_tc<EPI_BN_RELU, false, true><<<gE, blk, GEMM_SMEM>>>(
        x, W1, b1, bn1g, bn1b, bn1m, bn1v, nullptr, gar, nullptr, NB, NEMB, NIN);
    gemm_tc<EPI_BIAS, true, false><<<gE, blk, GEMM_SMEM>>>(
        gar, W2, b2, nullptr, nullptr, nullptr, nullptr, nullptr, gb, gbr, NB, NEMB, NEMB);
    gemm_tc<EPI_RES, true, false><<<gE, blk, GEMM_SMEM>>>(
        gbr, rbW + 0 * WS, rbb + 0 * NEMB, rbg + 0 * NEMB, rbbe + 0 * NEMB,
        rbm + 0 * NEMB, rbv + 0 * NEMB, gb, ga, gar, NB, NEMB, NEMB);
    gemm_tc<EPI_RES, false, false><<<gE, blk, GEMM_SMEM>>>(
        gar, rbW + 1 * WS, rbb + 1 * NEMB, rbg + 1 * NEMB, rbbe + 1 * NEMB,
        rbm + 1 * NEMB, rbv + 1 * NEMB, ga, gz, nullptr, NB, NEMB, NEMB);

    // vector quantizer
    vq_tc<<<NFLAT / 64, blk, VQ_SMEM>>>(gz, cb);
    gather_loss_kernel<<<NFLAT / 8, 256>>>(gz, cb, gb, gbr);
    finalize_kernel<<<1, 256>>>(out);

    // decoder
    gemm_tc<EPI_RES, true, false><<<gE, blk, GEMM_SMEM>>>(
        gbr, rbW + 2 * WS, rbb + 2 * NEMB, rbg + 2 * NEMB, rbbe + 2 * NEMB,
        rbm + 2 * NEMB, rbv + 2 * NEMB, gb, ga, gar, NB, NEMB, NEMB);
    gemm_tc<EPI_RES, true, false><<<gE, blk, GEMM_SMEM>>>(
        gar, rbW + 3 * WS, rbb + 3 * NEMB, rbg + 3 * NEMB, rbbe + 3 * NEMB,
        rbm + 3 * NEMB, rbv + 3 * NEMB, ga, gb, gbr, NB, NEMB, NEMB);
    gemm_tc<EPI_RES, false, false><<<gE, blk, GEMM_SMEM>>>(
        gbr, rbW + 4 * WS, rbb + 4 * NEMB, rbg + 4 * NEMB, rbbe + 4 * NEMB,
        rbm + 4 * NEMB, rbv + 4 * NEMB, gb, ga, nullptr, NB, NEMB, NEMB);

    gemm_tc<EPI_SIG, false, false><<<gD, blk, GEMM_SMEM>>>(
        ga, decW, decb, nullptr, nullptr, nullptr, nullptr, nullptr,
        out + 1, nullptr, NB, NIN, NEMB);
}

// round 5
// speedup vs baseline: 1.3060x; 1.3060x over previous
#include <cuda_runtime.h>
#include <cuda_bf16.h>
#include <math.h>
#include <stdint.h>

// ---------------- problem dims ----------------
#define NB    4096
#define NIN   8192
#define NEMB  1024
#define NK    4096
#define NCD   256
#define NFLAT 16384
#define OUT_PERP_OFF ((size_t)1 + (size_t)NB * (size_t)NIN)

#define EPI_BN_RELU 0
#define EPI_BIAS    1
#define EPI_RES     2
#define EPI_SIG     3

// ---------------- scratch (device globals) ----------------
__device__ float g_a   [(size_t)NB * NEMB];
__device__ float g_ar  [(size_t)NB * NEMB];
__device__ float g_z   [(size_t)NB * NEMB];
__device__ float g_cnorm[NK];
__device__ int   g_idx[NFLAT];
__device__ int   g_cnt[NK];
__device__ float g_losspart[NFLAT / 8];
// bf16 decoder-side scratch
__device__ __nv_bfloat16 g_wt2[(size_t)NEMB * NEMB];
__device__ __nv_bfloat16 g_wt3[(size_t)NEMB * NEMB];
__device__ __nv_bfloat16 g_wt4[(size_t)NEMB * NEMB];
__device__ __nv_bfloat16 g_wtd[(size_t)NIN * NEMB];
__device__ __nv_bfloat16 g_h1 [(size_t)NB * NEMB];
__device__ __nv_bfloat16 g_h1r[(size_t)NB * NEMB];
__device__ __nv_bfloat16 g_h2 [(size_t)NB * NEMB];
__device__ __nv_bfloat16 g_h2r[(size_t)NB * NEMB];

// ---------------- small helpers ----------------
__device__ __forceinline__ uint32_t rtf32_u(float x) {
    uint32_t r;
    asm("cvt.rna.tf32.f32 %0, %1;" : "=r"(r) : "f"(x));
    return r;
}
__device__ __forceinline__ float rtf32(float x) {
    return __uint_as_float(rtf32_u(x));
}
__device__ __forceinline__ void cp16(uint32_t dst, const void* src) {
    asm volatile("cp.async.cg.shared.global [%0], [%1], 16;" :: "r"(dst), "l"(src));
}
__device__ __forceinline__ void cp_commit() {
    asm volatile("cp.async.commit_group;");
}
template<int N>
__device__ __forceinline__ void cp_wait() {
    asm volatile("cp.async.wait_group %0;" :: "n"(N));
}
__device__ __forceinline__ void mma8(float* c, const uint32_t* a, const uint32_t* b) {
    asm volatile(
        "mma.sync.aligned.m16n8k8.row.col.f32.tf32.tf32.f32 "
        "{%0,%1,%2,%3},{%4,%5,%6,%7},{%8,%9},{%0,%1,%2,%3};"
        : "+f"(c[0]), "+f"(c[1]), "+f"(c[2]), "+f"(c[3])
        : "r"(a[0]), "r"(a[1]), "r"(a[2]), "r"(a[3]), "r"(b[0]), "r"(b[1]));
}
__device__ __forceinline__ void mma16(float* c, const uint32_t* a, const uint32_t* b) {
    asm volatile(
        "mma.sync.aligned.m16n8k16.row.col.f32.bf16.bf16.f32 "
        "{%0,%1,%2,%3},{%4,%5,%6,%7},{%8,%9},{%0,%1,%2,%3};"
        : "+f"(c[0]), "+f"(c[1]), "+f"(c[2]), "+f"(c[3])
        : "r"(a[0]), "r"(a[1]), "r"(a[2]), "r"(a[3]), "r"(b[0]), "r"(b[1]));
}

// ================= tf32 tensor-core GEMM (encoder) =================
// block tile 128x256, BK=32, 8 warps (2x4), warp tile 64x64, m16n8k8. (R3 proven)
#define TBM 128
#define TBN 256
#define TBK 32
#define A_STR 36
#define AS_SZ (TBM * A_STR)
#define BS_SZ (TBK * TBN)
#define GEMM_SMEM ((2 * AS_SZ + 2 * BS_SZ) * 4)

template<int EPI, bool WRELU>
__global__ void __launch_bounds__(256, 1)
gemm_tc(const float* __restrict__ A, const float* __restrict__ W,
        const float* __restrict__ bias,
        const float* __restrict__ gamma, const float* __restrict__ beta,
        const float* __restrict__ mean,  const float* __restrict__ var,
        const float* __restrict__ res,
        float* __restrict__ out0, float* __restrict__ out1,
        int M, int N, int K)
{
    extern __shared__ float smem[];
    float* As = smem;
    float* Bs = smem + 2 * AS_SZ;
    const uint32_t s_as = (uint32_t)__cvta_generic_to_shared(As);
    const uint32_t s_bs = (uint32_t)__cvta_generic_to_shared(Bs);

    const int tid  = threadIdx.x;
    const int lane = tid & 31;
    const int warp = tid >> 5;
    const int wm   = warp >> 2;
    const int wn   = warp & 3;
    const int row0 = blockIdx.y * TBM;
    const int col0 = blockIdx.x * TBN;
    const int l4   = lane >> 2;
    const int lm   = lane & 3;

    float acc[4][8][4];
#pragma unroll
    for (int mt = 0; mt < 4; mt++)
#pragma unroll
        for (int nt = 0; nt < 8; nt++)
#pragma unroll
            for (int q = 0; q < 4; q++) acc[mt][nt][q] = 0.f;

    const int iters = K / TBK;

    auto loadA = [&](int s, int k0) {
#pragma unroll
        for (int i = 0; i < 4; i++) {
            int idx = i * 256 + tid;
            int r = idx >> 3, kc = (idx & 7) << 2;
            cp16(s_as + (uint32_t)(s * AS_SZ + r * A_STR + kc) * 4,
                 A + (size_t)(row0 + r) * K + k0 + kc);
        }
    };
    auto loadB = [&](int s, int k0) {
#pragma unroll
        for (int i = 0; i < 8; i++) {
            int idx = i * 256 + tid;
            int k = idx >> 6, nc = (idx & 63) << 2;
            int nsw = nc ^ ((k & 3) << 3);
            cp16(s_bs + (uint32_t)(s * BS_SZ + k * TBN + nsw) * 4,
                 W + (size_t)(k0 + k) * N + col0 + nc);
        }
    };

    loadA(0, 0); loadB(0, 0); cp_commit();

    int s = 0;
    for (int it = 0; it < iters; it++) {
        if (it + 1 < iters) {
            loadA(s ^ 1, (it + 1) * TBK);
            loadB(s ^ 1, (it + 1) * TBK);
            cp_commit();
            cp_wait<1>();
        } else {
            cp_wait<0>();
        }
        __syncthreads();

        const float* as = As + s * AS_SZ;
        const float* bs = Bs + s * BS_SZ;
#pragma unroll
        for (int kk = 0; kk < TBK; kk += 8) {
            uint32_t af[4][4], bf[8][2];
#pragma unroll
            for (int mt = 0; mt < 4; mt++) {
                int r = wm * 64 + mt * 16 + l4;
                af[mt][0] = rtf32_u(as[r * A_STR + kk + lm]);
                af[mt][1] = rtf32_u(as[(r + 8) * A_STR + kk + lm]);
                af[mt][2] = rtf32_u(as[r * A_STR + kk + 4 + lm]);
                af[mt][3] = rtf32_u(as[(r + 8) * A_STR + kk + 4 + lm]);
            }
#pragma unroll
            for (int nt = 0; nt < 8; nt++) {
                int c   = wn * 64 + nt * 8 + l4;
                int csw = c ^ (lm << 3);
                bf[nt][0] = rtf32_u(bs[(kk + lm) * TBN + csw]);
                bf[nt][1] = rtf32_u(bs[(kk + 4 + lm) * TBN + csw]);
            }
#pragma unroll
            for (int mt = 0; mt < 4; mt++)
#pragma unroll
                for (int nt = 0; nt < 8; nt++)
                    mma8(acc[mt][nt], af[mt], bf[nt]);
        }
        __syncthreads();
        s ^= 1;
    }

    // ---- epilogue ----
#pragma unroll
    for (int nt = 0; nt < 8; nt++) {
        int c = col0 + wn * 64 + nt * 8 + (lm << 1);
        float b0 = bias[c], b1 = bias[c + 1];
        float g0 = 0.f, g1 = 0.f, be0 = 0.f, be1 = 0.f, m0 = 0.f, m1 = 0.f;
        if (EPI == EPI_BN_RELU || EPI == EPI_RES) {
            g0 = gamma[c]     * rsqrtf(var[c]     + 1e-5f);
            g1 = gamma[c + 1] * rsqrtf(var[c + 1] + 1e-5f);
            be0 = beta[c]; be1 = beta[c + 1];
            m0 = mean[c]; m1 = mean[c + 1];
        }
#pragma unroll
        for (int mt = 0; mt < 4; mt++) {
#pragma unroll
            for (int h = 0; h < 2; h++) {
                int r = row0 + wm * 64 + mt * 16 + l4 + h * 8;
                size_t off = (size_t)r * N + c;
                float x0 = acc[mt][nt][h * 2 + 0] + b0;
                float x1 = acc[mt][nt][h * 2 + 1] + b1;
                if (EPI == EPI_BN_RELU) {
                    x0 = fmaxf((x0 - m0) * g0 + be0, 0.f);
                    x1 = fmaxf((x1 - m1) * g1 + be1, 0.f);
                } else if (EPI == EPI_RES) {
                    float2 rv = *(const float2*)(res + off);
                    x0 = (x0 - m0) * g0 + be0 + rv.x;
                    x1 = (x1 - m1) * g1 + be1 + rv.y;
                }
                float r0 = rtf32(x0), r1 = rtf32(x1);
                float2 v; v.x = r0; v.y = r1;
                *(float2*)(out0 + off) = v;
                if (WRELU) {
                    float2 w; w.x = fmaxf(r0, 0.f); w.y = fmaxf(r1, 0.f);
                    *(float2*)(out1 + off) = w;
                }
            }
        }
    }
}

// ================= bf16 tensor-core GEMM (decoder) =================
// block tile 128x256, BK=64 (halves), 8 warps (2x4), warp tile 64x64, m16n8k16.
// A: activations [row][K] bf16; B: pre-transposed weights [n][K] bf16.
#define HBK  64
#define HSTR 72                              // 64 + 8 pad halves
#define HAS  (128 * HSTR)                    // halves per A stage
#define HBS  (256 * HSTR)                    // halves per B stage
#define BF_SMEM ((2 * (HAS + HBS)) * 2)      // 110592 B

template<int EPI, bool WRELU>
__global__ void __launch_bounds__(256, 1)
gemm_bf(const __nv_bfloat16* __restrict__ A, const __nv_bfloat16* __restrict__ WT,
        const float* __restrict__ bias,
        const float* __restrict__ gamma, const float* __restrict__ beta,
        const float* __restrict__ mean,  const float* __restrict__ var,
        const __nv_bfloat16* __restrict__ res,
        void* __restrict__ out0, __nv_bfloat16* __restrict__ out1,
        int M, int N, int K)
{
    extern __shared__ __nv_bfloat16 smemh[];
    __nv_bfloat16* AsH = smemh;
    __nv_bfloat16* BsH = smemh + 2 * HAS;
    const uint32_t s_as = (uint32_t)__cvta_generic_to_shared(AsH);
    const uint32_t s_bs = (uint32_t)__cvta_generic_to_shared(BsH);

    const int tid  = threadIdx.x;
    const int lane = tid & 31;
    const int warp = tid >> 5;
    const int wm   = warp >> 2;
    const int wn   = warp & 3;
    const int row0 = blockIdx.y * 128;
    const int col0 = blockIdx.x * 256;
    const int l4   = lane >> 2;
    const int lm   = lane & 3;

    float acc[4][8][4];
#pragma unroll
    for (int mt = 0; mt < 4; mt++)
#pragma unroll
        for (int nt = 0; nt < 8; nt++)
#pragma unroll
            for (int q = 0; q < 4; q++) acc[mt][nt][q] = 0.f;

    const int iters = K / HBK;

    auto loadA = [&](int s, int k0) {
#pragma unroll
        for (int i = 0; i < 4; i++) {
            int idx = i * 256 + tid;
            int r = idx >> 3, kc = (idx & 7) << 3;
            cp16(s_as + (uint32_t)(s * HAS + r * HSTR + kc) * 2,
                 A + (size_t)(row0 + r) * K + k0 + kc);
        }
    };
    auto loadB = [&](int s, int k0) {
#pragma unroll
        for (int i = 0; i < 8; i++) {
            int idx = i * 256 + tid;
            int n = idx >> 3, kc = (idx & 7) << 3;
            cp16(s_bs + (uint32_t)(s * HBS + n * HSTR + kc) * 2,
                 WT + (size_t)(col0 + n) * K + k0 + kc);
        }
    };

    loadA(0, 0); loadB(0, 0); cp_commit();

    int s = 0;
    for (int it = 0; it < iters; it++) {
        if (it + 1 < iters) {
            loadA(s ^ 1, (it + 1) * HBK);
            loadB(s ^ 1, (it + 1) * HBK);
            cp_commit();
            cp_wait<1>();
        } else {
            cp_wait<0>();
        }
        __syncthreads();

        const __nv_bfloat16* as = AsH + s * HAS;
        const __nv_bfloat16* bs = BsH + s * HBS;
#pragma unroll
        for (int kk = 0; kk < HBK; kk += 16) {
            uint32_t af[4][4], bf[8][2];
#pragma unroll
            for (int mt = 0; mt < 4; mt++) {
                int r = wm * 64 + mt * 16 + l4;
                af[mt][0] = *(const uint32_t*)&as[r * HSTR + kk + 2 * lm];
                af[mt][1] = *(const uint32_t*)&as[(r + 8) * HSTR + kk + 2 * lm];
                af[mt][2] = *(const uint32_t*)&as[r * HSTR + kk + 8 + 2 * lm];
                af[mt][3] = *(const uint32_t*)&as[(r + 8) * HSTR + kk + 8 + 2 * lm];
            }
#pragma unroll
            for (int nt = 0; nt < 8; nt++) {
                int c = wn * 64 + nt * 8 + l4;
                bf[nt][0] = *(const uint32_t*)&bs[c * HSTR + kk + 2 * lm];
                bf[nt][1] = *(const uint32_t*)&bs[c * HSTR + kk + 8 + 2 * lm];
            }
#pragma unroll
            for (int mt = 0; mt < 4; mt++)
#pragma unroll
                for (int nt = 0; nt < 8; nt++)
                    mma16(acc[mt][nt], af[mt], bf[nt]);
        }
        __syncthreads();
        s ^= 1;
    }

    // ---- epilogue ----
#pragma unroll
    for (int nt = 0; nt < 8; nt++) {
        int c = col0 + wn * 64 + nt * 8 + (lm << 1);
        float b0 = bias[c], b1 = bias[c + 1];
        float g0 = 0.f, g1 = 0.f, be0 = 0.f, be1 = 0.f, m0 = 0.f, m1 = 0.f;
        if (EPI == EPI_RES) {
            g0 = gamma[c]     * rsqrtf(var[c]     + 1e-5f);
            g1 = gamma[c + 1] * rsqrtf(var[c + 1] + 1e-5f);
            be0 = beta[c]; be1 = beta[c + 1];
            m0 = mean[c]; m1 = mean[c + 1];
        }
#pragma unroll
        for (int mt = 0; mt < 4; mt++) {
#pragma unroll
            for (int h = 0; h < 2; h++) {
                int r = row0 + wm * 64 + mt * 16 + l4 + h * 8;
                size_t off = (size_t)r * N + c;
                float x0 = acc[mt][nt][h * 2 + 0] + b0;
                float x1 = acc[mt][nt][h * 2 + 1] + b1;
                if (EPI == EPI_RES) {
                    __nv_bfloat162 rv = *(const __nv_bfloat162*)(res + off);
                    x0 = (x0 - m0) * g0 + be0 + __bfloat162float(rv.x);
                    x1 = (x1 - m1) * g1 + be1 + __bfloat162float(rv.y);
                    __nv_bfloat162 ov;
                    ov.x = __float2bfloat16_rn(x0);
                    ov.y = __float2bfloat16_rn(x1);
                    *(__nv_bfloat162*)((__nv_bfloat16*)out0 + off) = ov;
                    if (WRELU) {
                        __nv_bfloat162 rw;
                        rw.x = __float2bfloat16_rn(fmaxf(x0, 0.f));
                        rw.y = __float2bfloat16_rn(fmaxf(x1, 0.f));
                        *(__nv_bfloat162*)(out1 + off) = rw;
                    }
                } else { // EPI_SIG
                    float* o = (float*)out0;
                    o[off]     = 1.f / (1.f + expf(-x0));
                    o[off + 1] = 1.f / (1.f + expf(-x1));
                }
            }
        }
    }
}

// ---------------- weight transpose + bf16 round ----------------
__global__ void transpose_bf16(const float* __restrict__ W, __nv_bfloat16* __restrict__ WT,
                               int K, int N)
{
    __shared__ float t[32][33];
    int n0 = blockIdx.x * 32, k0 = blockIdx.y * 32;
    int tx = threadIdx.x, ty = threadIdx.y;   // 32 x 8
#pragma unroll
    for (int i = 0; i < 32; i += 8)
        t[ty + i][tx] = W[(size_t)(k0 + ty + i) * N + n0 + tx];
    __syncthreads();
#pragma unroll
    for (int i = 0; i < 32; i += 8)
        WT[(size_t)(n0 + ty + i) * K + k0 + tx] = __float2bfloat16_rn(t[tx][ty + i]);
}

// ---------------- VQ: tf32 mma distances + fused argmin (R3) ----------------
#define VB_STR 36
#define VBS_SZ (256 * VB_STR)
#define VQ_SMEM ((2 * AS_SZ + 2 * VBS_SZ) * 4)

__global__ void __launch_bounds__(256, 1)
vq_tc(const float* __restrict__ Z, const float* __restrict__ CB)
{
    extern __shared__ float smem[];
    float* As = smem;
    float* Bs = smem + 2 * AS_SZ;
    const uint32_t s_as = (uint32_t)__cvta_generic_to_shared(As);
    const uint32_t s_bs = (uint32_t)__cvta_generic_to_shared(Bs);
    __shared__ float sv[128][4];
    __shared__ int   si[128][4];

    const int tid  = threadIdx.x;
    const int lane = tid & 31;
    const int warp = tid >> 5;
    const int wm   = warp >> 2;
    const int wn   = warp & 3;
    const int row0 = blockIdx.x * 128;
    const int l4   = lane >> 2;
    const int lm   = lane & 3;

    float minv[4][2];
    int   mini[4][2];
#pragma unroll
    for (int mt = 0; mt < 4; mt++)
#pragma unroll
        for (int h = 0; h < 2; h++) { minv[mt][h] = 3.4e38f; mini[mt][h] = 0; }

    auto loadA = [&](int s, int k0) {
#pragma unroll
        for (int i = 0; i < 4; i++) {
            int idx = i * 256 + tid;
            int r = idx >> 3, kc = (idx & 7) << 2;
            cp16(s_as + (uint32_t)(s * AS_SZ + r * A_STR + kc) * 4,
                 Z + (size_t)(row0 + r) * NCD + k0 + kc);
        }
    };

    for (int ct = 0; ct < NK; ct += 256) {
        float acc[4][8][4];
#pragma unroll
        for (int mt = 0; mt < 4; mt++)
#pragma unroll
            for (int nt = 0; nt < 8; nt++)
#pragma unroll
                for (int q = 0; q < 4; q++) acc[mt][nt][q] = 0.f;

        auto loadB = [&](int s, int k0) {
#pragma unroll
            for (int i = 0; i < 8; i++) {
                int idx = i * 256 + tid;
                int code = idx >> 3, kc = (idx & 7) << 2;
                cp16(s_bs + (uint32_t)(s * VBS_SZ + code * VB_STR + kc) * 4,
                     CB + (size_t)(ct + code) * NCD + k0 + kc);
            }
        };

        loadA(0, 0); loadB(0, 0); cp_commit();
        int s = 0;
        const int iters = NCD / TBK;
        for (int it = 0; it < iters; it++) {
            if (it + 1 < iters) {
                loadA(s ^ 1, (it + 1) * TBK);
                loadB(s ^ 1, (it + 1) * TBK);
                cp_commit();
                cp_wait<1>();
            } else {
                cp_wait<0>();
            }
            __syncthreads();

            const float* as = As + s * AS_SZ;
            const float* bs = Bs + s * VBS_SZ;
#pragma unroll
            for (int kk = 0; kk < TBK; kk += 8) {
                uint32_t af[4][4], bf[8][2];
#pragma unroll
                for (int mt = 0; mt < 4; mt++) {
                    int r = wm * 64 + mt * 16 + l4;
                    af[mt][0] = rtf32_u(as[r * A_STR + kk + lm]);
                    af[mt][1] = rtf32_u(as[(r + 8) * A_STR + kk + lm]);
                    af[mt][2] = rtf32_u(as[r * A_STR + kk + 4 + lm]);
                    af[mt][3] = rtf32_u(as[(r + 8) * A_STR + kk + 4 + lm]);
                }
#pragma unroll
                for (int nt = 0; nt < 8; nt++) {
                    int cc = wn * 64 + nt * 8 + l4;
                    bf[nt][0] = rtf32_u(bs[cc * VB_STR + kk + lm]);
                    bf[nt][1] = rtf32_u(bs[cc * VB_STR + kk + 4 + lm]);
                }
#pragma unroll
                for (int mt = 0; mt < 4; mt++)
#pragma unroll
                    for (int nt = 0; nt < 8; nt++)
                        mma8(acc[mt][nt], af[mt], bf[nt]);
            }
            __syncthreads();
            s ^= 1;
        }

#pragma unroll
        for (int nt = 0; nt < 8; nt++) {
            int code = ct + wn * 64 + nt * 8 + (lm << 1);
            float cn0 = g_cnorm[code], cn1 = g_cnorm[code + 1];
#pragma unroll
            for (int mt = 0; mt < 4; mt++)
#pragma unroll
                for (int h = 0; h < 2; h++) {
                    float d0 = cn0 - 2.f * acc[mt][nt][h * 2 + 0];
                    float d1 = cn1 - 2.f * acc[mt][nt][h * 2 + 1];
                    if (d0 < minv[mt][h]) { minv[mt][h] = d0; mini[mt][h] = code; }
                    if (d1 < minv[mt][h]) { minv[mt][h] = d1; mini[mt][h] = code + 1; }
                }
        }
    }

#pragma unroll
    for (int mt = 0; mt < 4; mt++)
#pragma unroll
        for (int h = 0; h < 2; h++) {
            float v = minv[mt][h]; int ix = mini[mt][h];
#pragma unroll
            for (int o = 1; o <= 2; o <<= 1) {
                float vo = __shfl_xor_sync(0xffffffffu, v, o);
                int   io = __shfl_xor_sync(0xffffffffu, ix, o);
                if (vo < v || (vo == v && io < ix)) { v = vo; ix = io; }
            }
            if (lm == 0) {
                int rl = wm * 64 + mt * 16 + l4 + h * 8;
                sv[rl][wn] = v; si[rl][wn] = ix;
            }
        }
    __syncthreads();
    if (tid < 128) {
        float bv = sv[tid][0]; int bi = si[tid][0];
#pragma unroll
        for (int t = 1; t < 4; t++) {
            float v = sv[tid][t]; int k2 = si[tid][t];
            if (v < bv || (v == bv && k2 < bi)) { bv = v; bi = k2; }
        }
        g_idx[row0 + tid] = bi;
        atomicAdd(&g_cnt[bi], 1);
    }
}

// ---------------- misc kernels ----------------
__global__ void zero_cnt_kernel()
{
    int i = blockIdx.x * 256 + threadIdx.x;
    if (i < NK) g_cnt[i] = 0;
}

__global__ __launch_bounds__(256)
void cnorm_kernel(const float* __restrict__ CB)
{
    int warp = threadIdx.x >> 5, lane = threadIdx.x & 31;
    int code = blockIdx.x * 8 + warp;
    const float* c = CB + (size_t)code * NCD;
    float s = 0.f;
#pragma unroll
    for (int e = 0; e < 8; e++) { float v = rtf32(c[e * 32 + lane]); s += v * v; }
#pragma unroll
    for (int o = 16; o > 0; o >>= 1) s += __shfl_xor_sync(0xffffffffu, s, o);
    if (lane == 0) g_cnorm[code] = s;
}

// gather quantized (bf16 raw + relu copies) + fp32 loss partials
__global__ __launch_bounds__(256)
void gather_loss_kernel(const float* __restrict__ Z, const float* __restrict__ CB,
                        __nv_bfloat16* __restrict__ HQ, __nv_bfloat16* __restrict__ HQR)
{
    __shared__ float ws[8];
    int warp = threadIdx.x >> 5, lane = threadIdx.x & 31;
    int row  = blockIdx.x * 8 + warp;
    int id   = g_idx[row];
    const float* q = CB + (size_t)id * NCD;
    const float* z = Z + (size_t)row * NCD;
    __nv_bfloat16* o   = HQ  + (size_t)row * NCD;
    __nv_bfloat16* orl = HQR + (size_t)row * NCD;
    float s = 0.f;
#pragma unroll
    for (int e = 0; e < 8; e++) {
        int d = e * 32 + lane;
        float qq = q[d], zz = z[d];
        o[d]   = __float2bfloat16_rn(qq);
        orl[d] = __float2bfloat16_rn(fmaxf(qq, 0.f));
        float t = qq - zz;
        s += t * t;
    }
#pragma unroll
    for (int off = 16; off > 0; off >>= 1) s += __shfl_xor_sync(0xffffffffu, s, off);
    if (lane == 0) ws[warp] = s;
    __syncthreads();
    if (threadIdx.x == 0) {
        float t = 0.f;
#pragma unroll
        for (int w = 0; w < 8; w++) t += ws[w];
        g_losspart[blockIdx.x] = t;
    }
}

__global__ __launch_bounds__(256)
void finalize_kernel(float* __restrict__ out)
{
    __shared__ float red[256];
    int tid = threadIdx.x;

    float s = 0.f;
    for (int i = tid; i < NFLAT / 8; i += 256) s += g_losspart[i];
    red[tid] = s; __syncthreads();
    for (int o = 128; o > 0; o >>= 1) { if (tid < o) red[tid] += red[tid + o]; __syncthreads(); }
    float loss = red[0] * (1.25f / ((float)NB * (float)NEMB));
    __syncthreads();

    float e = 0.f;
    for (int i = tid; i < NK; i += 256) {
        float p = (float)g_cnt[i] * (1.0f / (float)NFLAT);
        e += p * logf(p + 1e-10f);
    }
    red[tid] = e; __syncthreads();
    for (int o = 128; o > 0; o >>= 1) { if (tid < o) red[tid] += red[tid + o]; __syncthreads(); }

    if (tid == 0) {
        out[0]            = loss;
        out[OUT_PERP_OFF] = expf(-red[0]);
    }
}

// ---------------- launch ----------------
extern "C" void kernel_launch(void* const* d_in, const int* in_sizes, int n_in,
                              void* d_out, int out_size)
{
    const float* x    = (const float*)d_in[0];
    const float* W1   = (const float*)d_in[1];
    const float* b1   = (const float*)d_in[2];
    const float* bn1g = (const float*)d_in[3];
    const float* bn1b = (const float*)d_in[4];
    const float* bn1m = (const float*)d_in[5];
    const float* bn1v = (const float*)d_in[6];
    const float* W2   = (const float*)d_in[7];
    const float* b2   = (const float*)d_in[8];
    const float* rbW  = (const float*)d_in[9];
    const float* rbb  = (const float*)d_in[10];
    const float* rbg  = (const float*)d_in[11];
    const float* rbbe = (const float*)d_in[12];
    const float* rbm  = (const float*)d_in[13];
    const float* rbv  = (const float*)d_in[14];
    const float* cb   = (const float*)d_in[15];
    const float* decW = (const float*)d_in[16];
    const float* decb = (const float*)d_in[17];
    float* out = (float*)d_out;

    float *ga, *gar, *gz;
    cudaGetSymbolAddress((void**)&ga,  g_a);
    cudaGetSymbolAddress((void**)&gar, g_ar);
    cudaGetSymbolAddress((void**)&gz,  g_z);
    __nv_bfloat16 *wt2, *wt3, *wt4, *wtd, *h1, *h1r, *h2, *h2r;
    cudaGetSymbolAddress((void**)&wt2, g_wt2);
    cudaGetSymbolAddress((void**)&wt3, g_wt3);
    cudaGetSymbolAddress((void**)&wt4, g_wt4);
    cudaGetSymbolAddress((void**)&wtd, g_wtd);
    cudaGetSymbolAddress((void**)&h1,  g_h1);
    cudaGetSymbolAddress((void**)&h1r, g_h1r);
    cudaGetSymbolAddress((void**)&h2,  g_h2);
    cudaGetSymbolAddress((void**)&h2r, g_h2r);

    cudaFuncSetAttribute(gemm_tc<EPI_BN_RELU, false>, cudaFuncAttributeMaxDynamicSharedMemorySize, GEMM_SMEM);
    cudaFuncSetAttribute(gemm_tc<EPI_BIAS,    true >, cudaFuncAttributeMaxDynamicSharedMemorySize, GEMM_SMEM);
    cudaFuncSetAttribute(gemm_tc<EPI_RES,     true >, cudaFuncAttributeMaxDynamicSharedMemorySize, GEMM_SMEM);
    cudaFuncSetAttribute(gemm_tc<EPI_RES,     false>, cudaFuncAttributeMaxDynamicSharedMemorySize, GEMM_SMEM);
    cudaFuncSetAttribute(gemm_bf<EPI_RES,     true >, cudaFuncAttributeMaxDynamicSharedMemorySize, BF_SMEM);
    cudaFuncSetAttribute(gemm_bf<EPI_RES,     false>, cudaFuncAttributeMaxDynamicSharedMemorySize, BF_SMEM);
    cudaFuncSetAttribute(gemm_bf<EPI_SIG,     false>, cudaFuncAttributeMaxDynamicSharedMemorySize, BF_SMEM);
    cudaFuncSetAttribute(vq_tc, cudaFuncAttributeMaxDynamicSharedMemorySize, VQ_SMEM);

    const size_t WS = (size_t)NEMB * NEMB;

    zero_cnt_kernel<<<(NK + 255) / 256, 256>>>();
    cnorm_kernel<<<NK / 8, 256>>>(cb);

    // decoder weight transposes (independent; run early)
    dim3 tb(32, 8);
    transpose_bf16<<<dim3(NEMB / 32, NEMB / 32), tb>>>(rbW + 2 * WS, wt2, NEMB, NEMB);
    transpose_bf16<<<dim3(NEMB / 32, NEMB / 32), tb>>>(rbW + 3 * WS, wt3, NEMB, NEMB);
    transpose_bf16<<<dim3(NEMB / 32, NEMB / 32), tb>>>(rbW + 4 * WS, wt4, NEMB, NEMB);
    transpose_bf16<<<dim3(NIN / 32,  NEMB / 32), tb>>>(decW, wtd, NEMB, NIN);

    dim3 blk(256);
    dim3 gE(NEMB / TBN, NB / TBM);   // 4 x 32
    dim3 gD(NIN / 256,  NB / 128);   // 32 x 32

    // encoder (tf32)
    gemm_tc<EPI_BN_RELU, false><<<gE, blk, GEMM_SMEM>>>(
        x, W1, b1, bn1g, bn1b, bn1m, bn1v, nullptr, gar, nullptr, NB, NEMB, NIN);
    gemm_tc<EPI_BIAS, true><<<gE, blk, GEMM_SMEM>>>(
        gar, W2, b2, nullptr, nullptr, nullptr, nullptr, nullptr, gz, ga, NB, NEMB, NEMB);
    gemm_tc<EPI_RES, true><<<gE, blk, GEMM_SMEM>>>(
        ga, rbW + 0 * WS, rbb + 0 * NEMB, rbg + 0 * NEMB, rbbe + 0 * NEMB,
        rbm + 0 * NEMB, rbv + 0 * NEMB, gz, ga, gar, NB, NEMB, NEMB);
    gemm_tc<EPI_RES, false><<<gE, blk, GEMM_SMEM>>>(
        gar, rbW + 1 * WS, rbb + 1 * NEMB, rbg + 1 * NEMB, rbbe + 1 * NEMB,
        rbm + 1 * NEMB, rbv + 1 * NEMB, ga, gz, nullptr, NB, NEMB, NEMB);

    // vector quantizer (tf32)
    vq_tc<<<NFLAT / 128, blk, VQ_SMEM>>>(gz, cb);
    gather_loss_kernel<<<NFLAT / 8, 256>>>(gz, cb, h1, h1r);
    finalize_kernel<<<1, 256>>>(out);

    // decoder (bf16)
    gemm_bf<EPI_RES, true><<<gE, blk, BF_SMEM>>>(
        h1r, wt2, rbb + 2 * NEMB, rbg + 2 * NEMB, rbbe + 2 * NEMB,
        rbm + 2 * NEMB, rbv + 2 * NEMB, h1, h2, h2r, NB, NEMB, NEMB);
    gemm_bf<EPI_RES, true><<<gE, blk, BF_SMEM>>>(
        h2r, wt3, rbb + 3 * NEMB, rbg + 3 * NEMB, rbbe + 3 * NEMB,
        rbm + 3 * NEMB, rbv + 3 * NEMB, h2, h1, h1r, NB, NEMB, NEMB);
    gemm_bf<EPI_RES, false><<<gE, blk, BF_SMEM>>>(
        h1r, wt4, rbb + 4 * NEMB, rbg + 4 * NEMB, rbbe + 4 * NEMB,
        rbm + 4 * NEMB, rbv + 4 * NEMB, h1, h2, nullptr, NB, NEMB, NEMB);
    gemm_bf<EPI_SIG, false><<<gD, blk, BF_SMEM>>>(
        h2, wtd, decb, nullptr, nullptr, nullptr, nullptr, nullptr,
        out + 1, nullptr, NB, NIN, NEMB);
}

// round 6
// speedup vs baseline: 1.7414x; 1.3334x over previous
#include <cuda_runtime.h>
#include <cuda_fp16.h>
#include <math.h>
#include <stdint.h>

// ---------------- problem dims ----------------
#define NB    4096
#define NIN   8192
#define NEMB  1024
#define NK    4096
#define NCD   256
#define NFLAT 16384
#define OUT_PERP_OFF ((size_t)1 + (size_t)NB * (size_t)NIN)

#define EPI_BN_RELU 0
#define EPI_BIAS    1
#define EPI_RES     2
#define EPI_SIG     3

// ---------------- scratch (device globals) ----------------
__device__ __half g_w1t[(size_t)NIN * NEMB];   // W1^T  [1024][8192]
__device__ __half g_w2t[(size_t)NEMB * NEMB];
__device__ __half g_wt0[(size_t)NEMB * NEMB];
__device__ __half g_wt1[(size_t)NEMB * NEMB];
__device__ __half g_wt2[(size_t)NEMB * NEMB];
__device__ __half g_wt3[(size_t)NEMB * NEMB];
__device__ __half g_wt4[(size_t)NEMB * NEMB];
__device__ __half g_wdt[(size_t)NIN * NEMB];   // decW^T [8192][1024]
__device__ __half g_cbh[(size_t)NK * NCD];
__device__ __half g_ha [(size_t)NB * NEMB];
__device__ __half g_har[(size_t)NB * NEMB];
__device__ __half g_hb [(size_t)NB * NEMB];
__device__ __half g_hbr[(size_t)NB * NEMB];
__device__ __half g_z  [(size_t)NB * NEMB];
__device__ float  g_cnorm[NK];
__device__ int    g_idx[NFLAT];
__device__ int    g_cnt[NK];
__device__ float  g_losspart[NFLAT / 8];

// ---------------- small helpers ----------------
__device__ __forceinline__ void cp16(uint32_t dst, const void* src) {
    asm volatile("cp.async.cg.shared.global [%0], [%1], 16;" :: "r"(dst), "l"(src));
}
__device__ __forceinline__ void cp_commit() {
    asm volatile("cp.async.commit_group;");
}
template<int N>
__device__ __forceinline__ void cp_wait() {
    asm volatile("cp.async.wait_group %0;" :: "n"(N));
}
__device__ __forceinline__ void mma16(float* c, const uint32_t* a, const uint32_t* b) {
    asm volatile(
        "mma.sync.aligned.m16n8k16.row.col.f32.f16.f16.f32 "
        "{%0,%1,%2,%3},{%4,%5,%6,%7},{%8,%9},{%0,%1,%2,%3};"
        : "+f"(c[0]), "+f"(c[1]), "+f"(c[2]), "+f"(c[3])
        : "r"(a[0]), "r"(a[1]), "r"(a[2]), "r"(a[3]), "r"(b[0]), "r"(b[1]));
}
__device__ __forceinline__ uint32_t pack_h2(float a, float b) {
    __half2 h = __floats2half2_rn(a, b);
    return *(uint32_t*)&h;
}

// ================= fp16 tensor-core GEMM =================
// block tile 128x256, BK=64 (k-halves), 8 warps (2x4), warp tile 64x64, m16n8k16.
// A: activations [row][K]; fp16 (A32=false) or raw fp32 packed at frag load (A32=true).
// B: pre-transposed fp16 weights [n][K].
#define HBK   64
#define HA_STR 72
#define HAS   (128 * HA_STR)
#define FA_STR 68
#define FAS   (128 * FA_STR)
#define HBS   (256 * HA_STR)
#define SMEM_H16 (2 * HAS * 2 + 2 * HBS * 2)   // 110592
#define SMEM_H32 (2 * FAS * 4 + 2 * HBS * 2)   // 143360

template<int EPI, bool WRELU, bool A32>
__global__ void __launch_bounds__(256, 1)
gemm_h(const void* __restrict__ Ain, const __half* __restrict__ WT,
       const float* __restrict__ bias,
       const float* __restrict__ gamma, const float* __restrict__ beta,
       const float* __restrict__ mean,  const float* __restrict__ var,
       const __half* __restrict__ res,
       void* __restrict__ out0, __half* __restrict__ out1,
       int M, int N, int K)
{
    extern __shared__ char smem[];
    const int ASZ = A32 ? (2 * FAS * 4) : (2 * HAS * 2);
    float*  Af = (float*)smem;
    __half* Ah = (__half*)smem;
    __half* Bh = (__half*)(smem + ASZ);
    const uint32_t s_a = (uint32_t)__cvta_generic_to_shared(smem);
    const uint32_t s_b = (uint32_t)__cvta_generic_to_shared(Bh);

    const int tid  = threadIdx.x;
    const int lane = tid & 31;
    const int warp = tid >> 5;
    const int wm   = warp >> 2;
    const int wn   = warp & 3;
    const int row0 = blockIdx.y * 128;
    const int col0 = blockIdx.x * 256;
    const int l4   = lane >> 2;
    const int lm   = lane & 3;

    float acc[4][8][4];
#pragma unroll
    for (int mt = 0; mt < 4; mt++)
#pragma unroll
        for (int nt = 0; nt < 8; nt++)
#pragma unroll
            for (int q = 0; q < 4; q++) acc[mt][nt][q] = 0.f;

    const int iters = K / HBK;

    auto loadA = [&](int s, int k0) {
        if (A32) {
            const float* A = (const float*)Ain;
#pragma unroll
            for (int i = 0; i < 8; i++) {
                int idx = i * 256 + tid;
                int r = idx >> 4, kc = (idx & 15) << 2;
                cp16(s_a + (uint32_t)(s * FAS + r * FA_STR + kc) * 4,
                     A + (size_t)(row0 + r) * K + k0 + kc);
            }
        } else {
            const __half* A = (const __half*)Ain;
#pragma unroll
            for (int i = 0; i < 4; i++) {
                int idx = i * 256 + tid;
                int r = idx >> 3, kc = (idx & 7) << 3;
                cp16(s_a + (uint32_t)(s * HAS + r * HA_STR + kc) * 2,
                     A + (size_t)(row0 + r) * K + k0 + kc);
            }
        }
    };
    auto loadB = [&](int s, int k0) {
#pragma unroll
        for (int i = 0; i < 8; i++) {
            int idx = i * 256 + tid;
            int n = idx >> 3, kc = (idx & 7) << 3;
            cp16(s_b + (uint32_t)(s * HBS + n * HA_STR + kc) * 2,
                 WT + (size_t)(col0 + n) * K + k0 + kc);
        }
    };

    loadA(0, 0); loadB(0, 0); cp_commit();

    int s = 0;
    for (int it = 0; it < iters; it++) {
        if (it + 1 < iters) {
            loadA(s ^ 1, (it + 1) * HBK);
            loadB(s ^ 1, (it + 1) * HBK);
            cp_commit();
            cp_wait<1>();
        } else {
            cp_wait<0>();
        }
        __syncthreads();

        const float*  af32 = Af + s * FAS;
        const __half* ah16 = Ah + s * HAS;
        const __half* bs   = Bh + s * HBS;
#pragma unroll
        for (int kk = 0; kk < HBK; kk += 16) {
            uint32_t af[4][4], bf[8][2];
#pragma unroll
            for (int mt = 0; mt < 4; mt++) {
                int r = wm * 64 + mt * 16 + l4;
                if (A32) {
                    float2 v0 = *(const float2*)&af32[r * FA_STR + kk + 2 * lm];
                    float2 v1 = *(const float2*)&af32[(r + 8) * FA_STR + kk + 2 * lm];
                    float2 v2 = *(const float2*)&af32[r * FA_STR + kk + 8 + 2 * lm];
                    float2 v3 = *(const float2*)&af32[(r + 8) * FA_STR + kk + 8 + 2 * lm];
                    af[mt][0] = pack_h2(v0.x, v0.y);
                    af[mt][1] = pack_h2(v1.x, v1.y);
                    af[mt][2] = pack_h2(v2.x, v2.y);
                    af[mt][3] = pack_h2(v3.x, v3.y);
                } else {
                    af[mt][0] = *(const uint32_t*)&ah16[r * HA_STR + kk + 2 * lm];
                    af[mt][1] = *(const uint32_t*)&ah16[(r + 8) * HA_STR + kk + 2 * lm];
                    af[mt][2] = *(const uint32_t*)&ah16[r * HA_STR + kk + 8 + 2 * lm];
                    af[mt][3] = *(const uint32_t*)&ah16[(r + 8) * HA_STR + kk + 8 + 2 * lm];
                }
            }
#pragma unroll
            for (int nt = 0; nt < 8; nt++) {
                int c = wn * 64 + nt * 8 + l4;
                bf[nt][0] = *(const uint32_t*)&bs[c * HA_STR + kk + 2 * lm];
                bf[nt][1] = *(const uint32_t*)&bs[c * HA_STR + kk + 8 + 2 * lm];
            }
#pragma unroll
            for (int mt = 0; mt < 4; mt++)
#pragma unroll
                for (int nt = 0; nt < 8; nt++)
                    mma16(acc[mt][nt], af[mt], bf[nt]);
        }
        __syncthreads();
        s ^= 1;
    }

    // ---- epilogue ----
#pragma unroll
    for (int nt = 0; nt < 8; nt++) {
        int c = col0 + wn * 64 + nt * 8 + (lm << 1);
        float b0 = bias[c], b1 = bias[c + 1];
        float g0 = 0.f, g1 = 0.f, be0 = 0.f, be1 = 0.f, m0 = 0.f, m1 = 0.f;
        if (EPI == EPI_BN_RELU || EPI == EPI_RES) {
            g0 = gamma[c]     * rsqrtf(var[c]     + 1e-5f);
            g1 = gamma[c + 1] * rsqrtf(var[c + 1] + 1e-5f);
            be0 = beta[c]; be1 = beta[c + 1];
            m0 = mean[c]; m1 = mean[c + 1];
        }
#pragma unroll
        for (int mt = 0; mt < 4; mt++) {
#pragma unroll
            for (int h = 0; h < 2; h++) {
                int r = row0 + wm * 64 + mt * 16 + l4 + h * 8;
                size_t off = (size_t)r * N + c;
                float x0 = acc[mt][nt][h * 2 + 0] + b0;
                float x1 = acc[mt][nt][h * 2 + 1] + b1;
                if (EPI == EPI_SIG) {
                    float* o = (float*)out0;
                    o[off]     = 1.f / (1.f + expf(-x0));
                    o[off + 1] = 1.f / (1.f + expf(-x1));
                    continue;
                }
                if (EPI == EPI_BN_RELU) {
                    x0 = fmaxf((x0 - m0) * g0 + be0, 0.f);
                    x1 = fmaxf((x1 - m1) * g1 + be1, 0.f);
                } else if (EPI == EPI_RES) {
                    __half2 rv = *(const __half2*)(res + off);
                    x0 = (x0 - m0) * g0 + be0 + __half2float(rv.x);
                    x1 = (x1 - m1) * g1 + be1 + __half2float(rv.y);
                }
                __half2 ov; ov.x = __float2half_rn(x0); ov.y = __float2half_rn(x1);
                *(__half2*)((__half*)out0 + off) = ov;
                if (WRELU) {
                    __half2 rw;
                    rw.x = __float2half_rn(fmaxf(x0, 0.f));
                    rw.y = __float2half_rn(fmaxf(x1, 0.f));
                    *(__half2*)(out1 + off) = rw;
                }
            }
        }
    }
}

// ================= VQ: fp16 mma distances + fused argmin =================
// 128 rows/CTA; z tile (128x256) resident in smem; codebook streamed in
// 64 chunks (16 code-tiles x 4 k-chunks), double-buffered.
#define AZ_STR 264
#define VQ_SMEM (128 * AZ_STR * 2 + 2 * HBS * 2)   // 67584 + 73728 = 141312

__global__ void __launch_bounds__(256, 1)
vq_h(const __half* __restrict__ Z, const __half* __restrict__ CBH)
{
    extern __shared__ char smem[];
    __half* Az = (__half*)smem;
    __half* Bh = (__half*)(smem + 128 * AZ_STR * 2);
    const uint32_t s_az = (uint32_t)__cvta_generic_to_shared(Az);
    const uint32_t s_b  = (uint32_t)__cvta_generic_to_shared(Bh);
    __shared__ float sv[128][4];
    __shared__ int   si[128][4];

    const int tid  = threadIdx.x;
    const int lane = tid & 31;
    const int warp = tid >> 5;
    const int wm   = warp >> 2;
    const int wn   = warp & 3;
    const int row0 = blockIdx.x * 128;
    const int l4   = lane >> 2;
    const int lm   = lane & 3;

    // resident z tile: 128 rows x 256 halves
#pragma unroll
    for (int i = 0; i < 16; i++) {
        int idx = i * 256 + tid;
        int r = idx >> 5, kc = (idx & 31) << 3;
        cp16(s_az + (uint32_t)(r * AZ_STR + kc) * 2,
             Z + (size_t)(row0 + r) * NCD + kc);
    }

    auto loadB = [&](int s, int chunk) {
        int ct = chunk >> 2, k0 = (chunk & 3) * 64;
#pragma unroll
        for (int i = 0; i < 8; i++) {
            int idx = i * 256 + tid;
            int code = idx >> 3, kc = (idx & 7) << 3;
            cp16(s_b + (uint32_t)(s * HBS + code * HA_STR + kc) * 2,
                 CBH + (size_t)(ct * 256 + code) * NCD + k0 + kc);
        }
    };

    loadB(0, 0); cp_commit();

    float minv[4][2];
    int   mini[4][2];
#pragma unroll
    for (int mt = 0; mt < 4; mt++)
#pragma unroll
        for (int h = 0; h < 2; h++) { minv[mt][h] = 3.4e38f; mini[mt][h] = 0; }

    float acc[4][8][4];
#pragma unroll
    for (int mt = 0; mt < 4; mt++)
#pragma unroll
        for (int nt = 0; nt < 8; nt++)
#pragma unroll
            for (int q = 0; q < 4; q++) acc[mt][nt][q] = 0.f;

    int s = 0;
    for (int c = 0; c < 64; c++) {
        if (c + 1 < 64) {
            loadB(s ^ 1, c + 1);
            cp_commit();
            cp_wait<1>();
        } else {
            cp_wait<0>();
        }
        __syncthreads();

        const __half* bs = Bh + s * HBS;
        const int kg = (c & 3) * 64;
#pragma unroll
        for (int kk = 0; kk < 64; kk += 16) {
            uint32_t af[4][4], bf[8][2];
#pragma unroll
            for (int mt = 0; mt < 4; mt++) {
                int r = wm * 64 + mt * 16 + l4;
                af[mt][0] = *(const uint32_t*)&Az[r * AZ_STR + kg + kk + 2 * lm];
                af[mt][1] = *(const uint32_t*)&Az[(r + 8) * AZ_STR + kg + kk + 2 * lm];
                af[mt][2] = *(const uint32_t*)&Az[r * AZ_STR + kg + kk + 8 + 2 * lm];
                af[mt][3] = *(const uint32_t*)&Az[(r + 8) * AZ_STR + kg + kk + 8 + 2 * lm];
            }
#pragma unroll
            for (int nt = 0; nt < 8; nt++) {
                int cc = wn * 64 + nt * 8 + l4;
                bf[nt][0] = *(const uint32_t*)&bs[cc * HA_STR + kk + 2 * lm];
                bf[nt][1] = *(const uint32_t*)&bs[cc * HA_STR + kk + 8 + 2 * lm];
            }
#pragma unroll
            for (int mt = 0; mt < 4; mt++)
#pragma unroll
                for (int nt = 0; nt < 8; nt++)
                    mma16(acc[mt][nt], af[mt], bf[nt]);
        }
        __syncthreads();
        s ^= 1;

        if ((c & 3) == 3) {
            int ct = (c >> 2) * 256;
#pragma unroll
            for (int nt = 0; nt < 8; nt++) {
                int code = ct + wn * 64 + nt * 8 + (lm << 1);
                float cn0 = g_cnorm[code], cn1 = g_cnorm[code + 1];
#pragma unroll
                for (int mt = 0; mt < 4; mt++)
#pragma unroll
                    for (int h = 0; h < 2; h++) {
                        float d0 = cn0 - 2.f * acc[mt][nt][h * 2 + 0];
                        float d1 = cn1 - 2.f * acc[mt][nt][h * 2 + 1];
                        if (d0 < minv[mt][h]) { minv[mt][h] = d0; mini[mt][h] = code; }
                        if (d1 < minv[mt][h]) { minv[mt][h] = d1; mini[mt][h] = code + 1; }
                        acc[mt][nt][h * 2 + 0] = 0.f;
                        acc[mt][nt][h * 2 + 1] = 0.f;
                    }
            }
        }
    }

    // quad lanes hold different codes for same rows -> shuffle-reduce
#pragma unroll
    for (int mt = 0; mt < 4; mt++)
#pragma unroll
        for (int h = 0; h < 2; h++) {
            float v = minv[mt][h]; int ix = mini[mt][h];
#pragma unroll
            for (int o = 1; o <= 2; o <<= 1) {
                float vo = __shfl_xor_sync(0xffffffffu, v, o);
                int   io = __shfl_xor_sync(0xffffffffu, ix, o);
                if (vo < v || (vo == v && io < ix)) { v = vo; ix = io; }
            }
            if (lm == 0) {
                int rl = wm * 64 + mt * 16 + l4 + h * 8;
                sv[rl][wn] = v; si[rl][wn] = ix;
            }
        }
    __syncthreads();
    if (tid < 128) {
        float bv = sv[tid][0]; int bi = si[tid][0];
#pragma unroll
        for (int t = 1; t < 4; t++) {
            float v = sv[tid][t]; int k2 = si[tid][t];
            if (v < bv || (v == bv && k2 < bi)) { bv = v; bi = k2; }
        }
        g_idx[row0 + tid] = bi;
        atomicAdd(&g_cnt[bi], 1);
    }
}

// ---------------- pre-pass kernels ----------------
__global__ void transpose_f16(const float* __restrict__ W, __half* __restrict__ WT,
                              int K, int N)
{
    __shared__ float t[32][33];
    int n0 = blockIdx.x * 32, k0 = blockIdx.y * 32;
    int tx = threadIdx.x, ty = threadIdx.y;   // 32 x 8
#pragma unroll
    for (int i = 0; i < 32; i += 8)
        t[ty + i][tx] = W[(size_t)(k0 + ty + i) * N + n0 + tx];
    __syncthreads();
#pragma unroll
    for (int i = 0; i < 32; i += 8)
        WT[(size_t)(n0 + ty + i) * K + k0 + tx] = __float2half_rn(t[tx][ty + i]);
}

__global__ void cvt_f16(const float* __restrict__ in, __half* __restrict__ out, int n4)
{
    int i = blockIdx.x * 256 + threadIdx.x;
    if (i < n4) {
        float4 v = ((const float4*)in)[i];
        __half2 a = __floats2half2_rn(v.x, v.y);
        __half2 b = __floats2half2_rn(v.z, v.w);
        ((__half2*)out)[2 * i]     = a;
        ((__half2*)out)[2 * i + 1] = b;
    }
}

__global__ void zero_cnt_kernel()
{
    int i = blockIdx.x * 256 + threadIdx.x;
    if (i < NK) g_cnt[i] = 0;
}

__global__ __launch_bounds__(256)
void cnorm_kernel(const __half* __restrict__ CBH)
{
    int warp = threadIdx.x >> 5, lane = threadIdx.x & 31;
    int code = blockIdx.x * 8 + warp;
    const __half* c = CBH + (size_t)code * NCD;
    float s = 0.f;
#pragma unroll
    for (int e = 0; e < 8; e++) { float v = __half2float(c[e * 32 + lane]); s += v * v; }
#pragma unroll
    for (int o = 16; o > 0; o >>= 1) s += __shfl_xor_sync(0xffffffffu, s, o);
    if (lane == 0) g_cnorm[code] = s;
}

// gather quantized (fp16 raw + relu) + fp32 loss partials
__global__ __launch_bounds__(256)
void gather_loss_kernel(const __half* __restrict__ Z, const float* __restrict__ CB,
                        __half* __restrict__ HQ, __half* __restrict__ HQR)
{
    __shared__ float ws[8];
    int warp = threadIdx.x >> 5, lane = threadIdx.x & 31;
    int row  = blockIdx.x * 8 + warp;
    int id   = g_idx[row];
    const float*  q = CB + (size_t)id * NCD;
    const __half* z = Z + (size_t)row * NCD;
    __half* o   = HQ  + (size_t)row * NCD;
    __half* orl = HQR + (size_t)row * NCD;
    float s = 0.f;
#pragma unroll
    for (int e = 0; e < 8; e++) {
        int d = e * 32 + lane;
        float qq = q[d], zz = __half2float(z[d]);
        o[d]   = __float2half_rn(qq);
        orl[d] = __float2half_rn(fmaxf(qq, 0.f));
        float t = qq - zz;
        s += t * t;
    }
#pragma unroll
    for (int off = 16; off > 0; off >>= 1) s += __shfl_xor_sync(0xffffffffu, s, off);
    if (lane == 0) ws[warp] = s;
    __syncthreads();
    if (threadIdx.x == 0) {
        float t = 0.f;
#pragma unroll
        for (int w = 0; w < 8; w++) t += ws[w];
        g_losspart[blockIdx.x] = t;
    }
}

__global__ __launch_bounds__(256)
void finalize_kernel(float* __restrict__ out)
{
    __shared__ float red[256];
    int tid = threadIdx.x;

    float s = 0.f;
    for (int i = tid; i < NFLAT / 8; i += 256) s += g_losspart[i];
    red[tid] = s; __syncthreads();
    for (int o = 128; o > 0; o >>= 1) { if (tid < o) red[tid] += red[tid + o]; __syncthreads(); }
    float loss = red[0] * (1.25f / ((float)NB * (float)NEMB));
    __syncthreads();

    float e = 0.f;
    for (int i = tid; i < NK; i += 256) {
        float p = (float)g_cnt[i] * (1.0f / (float)NFLAT);
        e += p * logf(p + 1e-10f);
    }
    red[tid] = e; __syncthreads();
    for (int o = 128; o > 0; o >>= 1) { if (tid < o) red[tid] += red[tid + o]; __syncthreads(); }

    if (tid == 0) {
        out[0]            = loss;
        out[OUT_PERP_OFF] = expf(-red[0]);
    }
}

// ---------------- launch ----------------
extern "C" void kernel_launch(void* const* d_in, const int* in_sizes, int n_in,
                              void* d_out, int out_size)
{
    const float* x    = (const float*)d_in[0];
    const float* W1   = (const float*)d_in[1];
    const float* b1   = (const float*)d_in[2];
    const float* bn1g = (const float*)d_in[3];
    const float* bn1b = (const float*)d_in[4];
    const float* bn1m = (const float*)d_in[5];
    const float* bn1v = (const float*)d_in[6];
    const float* W2   = (const float*)d_in[7];
    const float* b2   = (const float*)d_in[8];
    const float* rbW  = (const float*)d_in[9];
    const float* rbb  = (const float*)d_in[10];
    const float* rbg  = (const float*)d_in[11];
    const float* rbbe = (const float*)d_in[12];
    const float* rbm  = (const float*)d_in[13];
    const float* rbv  = (const float*)d_in[14];
    const float* cb   = (const float*)d_in[15];
    const float* decW = (const float*)d_in[16];
    const float* decb = (const float*)d_in[17];
    float* out = (float*)d_out;

    __half *w1t, *w2t, *wt0, *wt1, *wt2, *wt3, *wt4, *wdt, *cbh;
    __half *ha, *har, *hb, *hbr, *gz;
    cudaGetSymbolAddress((void**)&w1t, g_w1t);
    cudaGetSymbolAddress((void**)&w2t, g_w2t);
    cudaGetSymbolAddress((void**)&wt0, g_wt0);
    cudaGetSymbolAddress((void**)&wt1, g_wt1);
    cudaGetSymbolAddress((void**)&wt2, g_wt2);
    cudaGetSymbolAddress((void**)&wt3, g_wt3);
    cudaGetSymbolAddress((void**)&wt4, g_wt4);
    cudaGetSymbolAddress((void**)&wdt, g_wdt);
    cudaGetSymbolAddress((void**)&cbh, g_cbh);
    cudaGetSymbolAddress((void**)&ha,  g_ha);
    cudaGetSymbolAddress((void**)&har, g_har);
    cudaGetSymbolAddress((void**)&hb,  g_hb);
    cudaGetSymbolAddress((void**)&hbr, g_hbr);
    cudaGetSymbolAddress((void**)&gz,  g_z);

    cudaFuncSetAttribute(gemm_h<EPI_BN_RELU, false, true >, cudaFuncAttributeMaxDynamicSharedMemorySize, SMEM_H32);
    cudaFuncSetAttribute(gemm_h<EPI_BIAS,    true,  false>, cudaFuncAttributeMaxDynamicSharedMemorySize, SMEM_H16);
    cudaFuncSetAttribute(gemm_h<EPI_RES,     true,  false>, cudaFuncAttributeMaxDynamicSharedMemorySize, SMEM_H16);
    cudaFuncSetAttribute(gemm_h<EPI_RES,     false, false>, cudaFuncAttributeMaxDynamicSharedMemorySize, SMEM_H16);
    cudaFuncSetAttribute(gemm_h<EPI_SIG,     false, false>, cudaFuncAttributeMaxDynamicSharedMemorySize, SMEM_H16);
    cudaFuncSetAttribute(vq_h, cudaFuncAttributeMaxDynamicSharedMemorySize, VQ_SMEM);

    const size_t WS = (size_t)NEMB * NEMB;
    dim3 tb(32, 8);
    dim3 blk(256);
    dim3 gE(NEMB / 256, NB / 128);   // 4 x 32
    dim3 gD(NIN / 256,  NB / 128);   // 32 x 32

    zero_cnt_kernel<<<(NK + 255) / 256, 256>>>();
    cvt_f16<<<(NK * NCD / 4 + 255) / 256, 256>>>(cb, cbh, NK * NCD / 4);
    cnorm_kernel<<<NK / 8, 256>>>(cbh);

    // weight transposes (fp32 [K][N] -> fp16 [N][K])
    transpose_f16<<<dim3(NEMB / 32, NIN / 32),  tb>>>(W1, w1t, NIN, NEMB);
    transpose_f16<<<dim3(NEMB / 32, NEMB / 32), tb>>>(W2, w2t, NEMB, NEMB);
    transpose_f16<<<dim3(NEMB / 32, NEMB / 32), tb>>>(rbW + 0 * WS, wt0, NEMB, NEMB);
    transpose_f16<<<dim3(NEMB / 32, NEMB / 32), tb>>>(rbW + 1 * WS, wt1, NEMB, NEMB);
    transpose_f16<<<dim3(NEMB / 32, NEMB / 32), tb>>>(rbW + 2 * WS, wt2, NEMB, NEMB);
    transpose_f16<<<dim3(NEMB / 32, NEMB / 32), tb>>>(rbW + 3 * WS, wt3, NEMB, NEMB);
    transpose_f16<<<dim3(NEMB / 32, NEMB / 32), tb>>>(rbW + 4 * WS, wt4, NEMB, NEMB);
    transpose_f16<<<dim3(NIN / 32,  NEMB / 32), tb>>>(decW, wdt, NEMB, NIN);

    // encoder (fp16 mma; enc1 reads fp32 x and packs at fragment load)
    gemm_h<EPI_BN_RELU, false, true><<<gE, blk, SMEM_H32>>>(
        x, w1t, b1, bn1g, bn1b, bn1m, bn1v, nullptr, har, nullptr, NB, NEMB, NIN);
    gemm_h<EPI_BIAS, true, false><<<gE, blk, SMEM_H16>>>(
        har, w2t, b2, nullptr, nullptr, nullptr, nullptr, nullptr, hb, hbr, NB, NEMB, NEMB);
    gemm_h<EPI_RES, true, false><<<gE, blk, SMEM_H16>>>(
        hbr, wt0, rbb + 0 * NEMB, rbg + 0 * NEMB, rbbe + 0 * NEMB,
        rbm + 0 * NEMB, rbv + 0 * NEMB, hb, ha, har, NB, NEMB, NEMB);
    gemm_h<EPI_RES, false, false><<<gE, blk, SMEM_H16>>>(
        har, wt1, rbb + 1 * NEMB, rbg + 1 * NEMB, rbbe + 1 * NEMB,
        rbm + 1 * NEMB, rbv + 1 * NEMB, ha, gz, nullptr, NB, NEMB, NEMB);

    // vector quantizer
    vq_h<<<NFLAT / 128, blk, VQ_SMEM>>>(gz, cbh);
    gather_loss_kernel<<<NFLAT / 8, 256>>>(gz, cb, hb, hbr);
    finalize_kernel<<<1, 256>>>(out);

    // decoder
    gemm_h<EPI_RES, true, false><<<gE, blk, SMEM_H16>>>(
        hbr, wt2, rbb + 2 * NEMB, rbg + 2 * NEMB, rbbe + 2 * NEMB,
        rbm + 2 * NEMB, rbv + 2 * NEMB, hb, ha, har, NB, NEMB, NEMB);
    gemm_h<EPI_RES, true, false><<<gE, blk, SMEM_H16>>>(
        har, wt3, rbb + 3 * NEMB, rbg + 3 * NEMB, rbbe + 3 * NEMB,
        rbm + 3 * NEMB, rbv + 3 * NEMB, ha, hb, hbr, NB, NEMB, NEMB);
    gemm_h<EPI_RES, false, false><<<gE, blk, SMEM_H16>>>(
        hbr, wt4, rbb + 4 * NEMB, rbg + 4 * NEMB, rbbe + 4 * NEMB,
        rbm + 4 * NEMB, rbv + 4 * NEMB, hb, ha, nullptr, NB, NEMB, NEMB);
    gemm_h<EPI_SIG, false, false><<<gD, blk, SMEM_H16>>>(
        ha, wdt, decb, nullptr, nullptr, nullptr, nullptr, nullptr,
        out + 1, nullptr, NB, NIN, NEMB);
}

// round 7
// speedup vs baseline: 1.7655x; 1.0139x over previous
#include <cuda_runtime.h>
#include <cuda_fp16.h>
#include <math.h>
#include <stdint.h>

// ---------------- problem dims ----------------
#define NB    4096
#define NIN   8192
#define NEMB  1024
#define NK    4096
#define NCD   256
#define NFLAT 16384
#define OUT_PERP_OFF ((size_t)1 + (size_t)NB * (size_t)NIN)

#define EPI_BN_RELU 0
#define EPI_BIAS    1
#define EPI_RES     2
#define EPI_SIG     3

// ---------------- scratch (device globals) ----------------
__device__ __half g_w1t[(size_t)NIN * NEMB];
__device__ __half g_w2t[(size_t)NEMB * NEMB];
__device__ __half g_wt0[(size_t)NEMB * NEMB];
__device__ __half g_wt1[(size_t)NEMB * NEMB];
__device__ __half g_wt2[(size_t)NEMB * NEMB];
__device__ __half g_wt3[(size_t)NEMB * NEMB];
__device__ __half g_wt4[(size_t)NEMB * NEMB];
__device__ __half g_wdt[(size_t)NIN * NEMB];
__device__ __half g_cbh[(size_t)NK * NCD];
__device__ __half g_ha [(size_t)NB * NEMB];
__device__ __half g_har[(size_t)NB * NEMB];
__device__ __half g_hb [(size_t)NB * NEMB];
__device__ __half g_hbr[(size_t)NB * NEMB];
__device__ __half g_z  [(size_t)NB * NEMB];
__device__ float  g_cnorm[NK];
__device__ int    g_idx[NFLAT];
__device__ int    g_cnt[NK];
__device__ float  g_losspart[NFLAT / 8];

// ---------------- small helpers ----------------
__device__ __forceinline__ void cp16(uint32_t dst, const void* src) {
    asm volatile("cp.async.cg.shared.global [%0], [%1], 16;" :: "r"(dst), "l"(src));
}
__device__ __forceinline__ void cp_commit() {
    asm volatile("cp.async.commit_group;");
}
template<int N>
__device__ __forceinline__ void cp_wait() {
    asm volatile("cp.async.wait_group %0;" :: "n"(N));
}
__device__ __forceinline__ void mma16(float* c, const uint32_t* a, const uint32_t* b) {
    asm volatile(
        "mma.sync.aligned.m16n8k16.row.col.f32.f16.f16.f32 "
        "{%0,%1,%2,%3},{%4,%5,%6,%7},{%8,%9},{%0,%1,%2,%3};"
        : "+f"(c[0]), "+f"(c[1]), "+f"(c[2]), "+f"(c[3])
        : "r"(a[0]), "r"(a[1]), "r"(a[2]), "r"(a[3]), "r"(b[0]), "r"(b[1]));
}
__device__ __forceinline__ void ldsm4(uint32_t& r0, uint32_t& r1, uint32_t& r2, uint32_t& r3,
                                      uint32_t addr) {
    asm volatile("ldmatrix.sync.aligned.m8n8.x4.shared.b16 {%0,%1,%2,%3}, [%4];"
                 : "=r"(r0), "=r"(r1), "=r"(r2), "=r"(r3) : "r"(addr));
}
__device__ __forceinline__ uint32_t pack_h2(float a, float b) {
    __half2 h = __floats2half2_rn(a, b);
    return *(uint32_t*)&h;
}

// ================= fp16 tensor-core GEMM =================
// block tile 128x256, BK=64, 8 warps (2x4), warp tile 64x64, m16n8k16, ldmatrix frags.
#define HBK   64
#define HA_STR 72
#define HAS   (128 * HA_STR)
#define FA_STR 68
#define FAS   (128 * FA_STR)
#define HBS   (256 * HA_STR)
#define SMEM_H16 (2 * HAS * 2 + 2 * HBS * 2)
#define SMEM_H32 (2 * FAS * 4 + 2 * HBS * 2)

template<int EPI, bool WRELU, bool A32>
__global__ void __launch_bounds__(256, 1)
gemm_h(const void* __restrict__ Ain, const __half* __restrict__ WT,
       const float* __restrict__ bias,
       const float* __restrict__ gamma, const float* __restrict__ beta,
       const float* __restrict__ mean,  const float* __restrict__ var,
       const __half* __restrict__ res,
       void* __restrict__ out0, __half* __restrict__ out1,
       int M, int N, int K)
{
    extern __shared__ char smem[];
    const int ASZ = A32 ? (2 * FAS * 4) : (2 * HAS * 2);
    float*  Af = (float*)smem;
    __half* Bh = (__half*)(smem + ASZ);
    const uint32_t s_a = (uint32_t)__cvta_generic_to_shared(smem);
    const uint32_t s_b = (uint32_t)__cvta_generic_to_shared(Bh);

    const int tid  = threadIdx.x;
    const int lane = tid & 31;
    const int warp = tid >> 5;
    const int wm   = warp >> 2;
    const int wn   = warp & 3;
    const int row0 = blockIdx.y * 128;
    const int col0 = blockIdx.x * 256;
    const int l4   = lane >> 2;
    const int lm   = lane & 3;
    const int t8   = lane >> 3;          // tile id inside ldmatrix.x4
    const int jr   = lane & 7;           // row inside tile

    // ldmatrix per-lane base addresses (byte offsets into stage 0)
    uint32_t aBase[4], bBase[4];
#pragma unroll
    for (int mt = 0; mt < 4; mt++) {
        int r = wm * 64 + mt * 16 + ((t8 & 1) << 3) + jr;
        int c = (t8 >> 1) << 3;
        aBase[mt] = s_a + (uint32_t)(r * HA_STR + c) * 2;
    }
#pragma unroll
    for (int p = 0; p < 4; p++) {
        int r = wn * 64 + (2 * p + (t8 >> 1)) * 8 + jr;
        int c = (t8 & 1) << 3;
        bBase[p] = s_b + (uint32_t)(r * HA_STR + c) * 2;
    }

    float acc[4][8][4];
#pragma unroll
    for (int mt = 0; mt < 4; mt++)
#pragma unroll
        for (int nt = 0; nt < 8; nt++)
#pragma unroll
            for (int q = 0; q < 4; q++) acc[mt][nt][q] = 0.f;

    const int iters = K / HBK;

    auto loadA = [&](int s, int k0) {
        if (A32) {
            const float* A = (const float*)Ain;
#pragma unroll
            for (int i = 0; i < 8; i++) {
                int idx = i * 256 + tid;
                int r = idx >> 4, kc = (idx & 15) << 2;
                cp16(s_a + (uint32_t)(s * FAS + r * FA_STR + kc) * 4,
                     A + (size_t)(row0 + r) * K + k0 + kc);
            }
        } else {
            const __half* A = (const __half*)Ain;
#pragma unroll
            for (int i = 0; i < 4; i++) {
                int idx = i * 256 + tid;
                int r = idx >> 3, kc = (idx & 7) << 3;
                cp16(s_a + (uint32_t)(s * HAS + r * HA_STR + kc) * 2,
                     A + (size_t)(row0 + r) * K + k0 + kc);
            }
        }
    };
    auto loadB = [&](int s, int k0) {
#pragma unroll
        for (int i = 0; i < 8; i++) {
            int idx = i * 256 + tid;
            int n = idx >> 3, kc = (idx & 7) << 3;
            cp16(s_b + (uint32_t)(s * HBS + n * HA_STR + kc) * 2,
                 WT + (size_t)(col0 + n) * K + k0 + kc);
        }
    };

    loadA(0, 0); loadB(0, 0); cp_commit();

    int s = 0;
    for (int it = 0; it < iters; it++) {
        if (it + 1 < iters) {
            loadA(s ^ 1, (it + 1) * HBK);
            loadB(s ^ 1, (it + 1) * HBK);
            cp_commit();
            cp_wait<1>();
        } else {
            cp_wait<0>();
        }
        __syncthreads();

        const float* af32 = Af + s * FAS;
        const uint32_t aOff = (uint32_t)s * (HAS * 2);
        const uint32_t bOff = (uint32_t)s * (HBS * 2);
#pragma unroll
        for (int kk = 0; kk < HBK; kk += 16) {
            uint32_t af[4][4], bf[8][2];
#pragma unroll
            for (int mt = 0; mt < 4; mt++) {
                if (A32) {
                    int r = wm * 64 + mt * 16 + l4;
                    float2 v0 = *(const float2*)&af32[r * FA_STR + kk + 2 * lm];
                    float2 v1 = *(const float2*)&af32[(r + 8) * FA_STR + kk + 2 * lm];
                    float2 v2 = *(const float2*)&af32[r * FA_STR + kk + 8 + 2 * lm];
                    float2 v3 = *(const float2*)&af32[(r + 8) * FA_STR + kk + 8 + 2 * lm];
                    af[mt][0] = pack_h2(v0.x, v0.y);
                    af[mt][1] = pack_h2(v1.x, v1.y);
                    af[mt][2] = pack_h2(v2.x, v2.y);
                    af[mt][3] = pack_h2(v3.x, v3.y);
                } else {
                    ldsm4(af[mt][0], af[mt][1], af[mt][2], af[mt][3],
                          aBase[mt] + aOff + (uint32_t)kk * 2);
                }
            }
#pragma unroll
            for (int p = 0; p < 4; p++)
                ldsm4(bf[2 * p][0], bf[2 * p][1], bf[2 * p + 1][0], bf[2 * p + 1][1],
                      bBase[p] + bOff + (uint32_t)kk * 2);
#pragma unroll
            for (int mt = 0; mt < 4; mt++)
#pragma unroll
                for (int nt = 0; nt < 8; nt++)
                    mma16(acc[mt][nt], af[mt], bf[nt]);
        }
        __syncthreads();
        s ^= 1;
    }

    // ---- epilogue ----
#pragma unroll
    for (int nt = 0; nt < 8; nt++) {
        int c = col0 + wn * 64 + nt * 8 + (lm << 1);
        float b0 = bias[c], b1 = bias[c + 1];
        float g0 = 0.f, g1 = 0.f, be0 = 0.f, be1 = 0.f, m0 = 0.f, m1 = 0.f;
        if (EPI == EPI_BN_RELU || EPI == EPI_RES) {
            g0 = gamma[c]     * rsqrtf(var[c]     + 1e-5f);
            g1 = gamma[c + 1] * rsqrtf(var[c + 1] + 1e-5f);
            be0 = beta[c]; be1 = beta[c + 1];
            m0 = mean[c]; m1 = mean[c + 1];
        }
#pragma unroll
        for (int mt = 0; mt < 4; mt++) {
#pragma unroll
            for (int h = 0; h < 2; h++) {
                int r = row0 + wm * 64 + mt * 16 + l4 + h * 8;
                size_t off = (size_t)r * N + c;
                float x0 = acc[mt][nt][h * 2 + 0] + b0;
                float x1 = acc[mt][nt][h * 2 + 1] + b1;
                if (EPI == EPI_SIG) {
                    float* o = (float*)out0;
                    o[off]     = 1.f / (1.f + expf(-x0));
                    o[off + 1] = 1.f / (1.f + expf(-x1));
                    continue;
                }
                if (EPI == EPI_BN_RELU) {
                    x0 = fmaxf((x0 - m0) * g0 + be0, 0.f);
                    x1 = fmaxf((x1 - m1) * g1 + be1, 0.f);
                } else if (EPI == EPI_RES) {
                    __half2 rv = *(const __half2*)(res + off);
                    x0 = (x0 - m0) * g0 + be0 + __half2float(rv.x);
                    x1 = (x1 - m1) * g1 + be1 + __half2float(rv.y);
                }
                __half2 ov; ov.x = __float2half_rn(x0); ov.y = __float2half_rn(x1);
                *(__half2*)((__half*)out0 + off) = ov;
                if (WRELU) {
                    __half2 rw;
                    rw.x = __float2half_rn(fmaxf(x0, 0.f));
                    rw.y = __float2half_rn(fmaxf(x1, 0.f));
                    *(__half2*)(out1 + off) = rw;
                }
            }
        }
    }
}

// ================= VQ: fp16 mma distances + fused argmin =================
#define AZ_STR 264
#define VQ_SMEM (128 * AZ_STR * 2 + 2 * HBS * 2)

__global__ void __launch_bounds__(256, 1)
vq_h(const __half* __restrict__ Z, const __half* __restrict__ CBH)
{
    extern __shared__ char smem[];
    __half* Az = (__half*)smem;
    __half* Bh = (__half*)(smem + 128 * AZ_STR * 2);
    const uint32_t s_az = (uint32_t)__cvta_generic_to_shared(Az);
    const uint32_t s_b  = (uint32_t)__cvta_generic_to_shared(Bh);
    __shared__ float sv[128][4];
    __shared__ int   si[128][4];

    const int tid  = threadIdx.x;
    const int lane = tid & 31;
    const int warp = tid >> 5;
    const int wm   = warp >> 2;
    const int wn   = warp & 3;
    const int row0 = blockIdx.x * 128;
    const int l4   = lane >> 2;
    const int lm   = lane & 3;
    const int t8   = lane >> 3;
    const int jr   = lane & 7;

    uint32_t aBase[4], bBase[4];
#pragma unroll
    for (int mt = 0; mt < 4; mt++) {
        int r = wm * 64 + mt * 16 + ((t8 & 1) << 3) + jr;
        int c = (t8 >> 1) << 3;
        aBase[mt] = s_az + (uint32_t)(r * AZ_STR + c) * 2;
    }
#pragma unroll
    for (int p = 0; p < 4; p++) {
        int r = wn * 64 + (2 * p + (t8 >> 1)) * 8 + jr;
        int c = (t8 & 1) << 3;
        bBase[p] = s_b + (uint32_t)(r * HA_STR + c) * 2;
    }

    // resident z tile: 128 rows x 256 halves
#pragma unroll
    for (int i = 0; i < 16; i++) {
        int idx = i * 256 + tid;
        int r = idx >> 5, kc = (idx & 31) << 3;
        cp16(s_az + (uint32_t)(r * AZ_STR + kc) * 2,
             Z + (size_t)(row0 + r) * NCD + kc);
    }

    auto loadB = [&](int s, int chunk) {
        int ct = chunk >> 2, k0 = (chunk & 3) * 64;
#pragma unroll
        for (int i = 0; i < 8; i++) {
            int idx = i * 256 + tid;
            int code = idx >> 3, kc = (idx & 7) << 3;
            cp16(s_b + (uint32_t)(s * HBS + code * HA_STR + kc) * 2,
                 CBH + (size_t)(ct * 256 + code) * NCD + k0 + kc);
        }
    };

    loadB(0, 0); cp_commit();

    float minv[4][2];
    int   mini[4][2];
#pragma unroll
    for (int mt = 0; mt < 4; mt++)
#pragma unroll
        for (int h = 0; h < 2; h++) { minv[mt][h] = 3.4e38f; mini[mt][h] = 0; }

    float acc[4][8][4];
#pragma unroll
    for (int mt = 0; mt < 4; mt++)
#pragma unroll
        for (int nt = 0; nt < 8; nt++)
#pragma unroll
            for (int q = 0; q < 4; q++) acc[mt][nt][q] = 0.f;

    int s = 0;
    for (int c = 0; c < 64; c++) {
        if (c + 1 < 64) {
            loadB(s ^ 1, c + 1);
            cp_commit();
            cp_wait<1>();
        } else {
            cp_wait<0>();
        }
        __syncthreads();

        const uint32_t bOff = (uint32_t)s * (HBS * 2);
        const int kg = (c & 3) * 64;
#pragma unroll
        for (int kk = 0; kk < 64; kk += 16) {
            uint32_t af[4][4], bf[8][2];
#pragma unroll
            for (int mt = 0; mt < 4; mt++)
                ldsm4(af[mt][0], af[mt][1], af[mt][2], af[mt][3],
                      aBase[mt] + (uint32_t)(kg + kk) * 2);
#pragma unroll
            for (int p = 0; p < 4; p++)
                ldsm4(bf[2 * p][0], bf[2 * p][1], bf[2 * p + 1][0], bf[2 * p + 1][1],
                      bBase[p] + bOff + (uint32_t)kk * 2);
#pragma unroll
            for (int mt = 0; mt < 4; mt++)
#pragma unroll
                for (int nt = 0; nt < 8; nt++)
                    mma16(acc[mt][nt], af[mt], bf[nt]);
        }
        __syncthreads();
        s ^= 1;

        if ((c & 3) == 3) {
            int ct = (c >> 2) * 256;
#pragma unroll
            for (int nt = 0; nt < 8; nt++) {
                int code = ct + wn * 64 + nt * 8 + (lm << 1);
                float cn0 = g_cnorm[code], cn1 = g_cnorm[code + 1];
#pragma unroll
                for (int mt = 0; mt < 4; mt++)
#pragma unroll
                    for (int h = 0; h < 2; h++) {
                        float d0 = cn0 - 2.f * acc[mt][nt][h * 2 + 0];
                        float d1 = cn1 - 2.f * acc[mt][nt][h * 2 + 1];
                        if (d0 < minv[mt][h]) { minv[mt][h] = d0; mini[mt][h] = code; }
                        if (d1 < minv[mt][h]) { minv[mt][h] = d1; mini[mt][h] = code + 1; }
                        acc[mt][nt][h * 2 + 0] = 0.f;
                        acc[mt][nt][h * 2 + 1] = 0.f;
                    }
            }
        }
    }

#pragma unroll
    for (int mt = 0; mt < 4; mt++)
#pragma unroll
        for (int h = 0; h < 2; h++) {
            float v = minv[mt][h]; int ix = mini[mt][h];
#pragma unroll
            for (int o = 1; o <= 2; o <<= 1) {
                float vo = __shfl_xor_sync(0xffffffffu, v, o);
                int   io = __shfl_xor_sync(0xffffffffu, ix, o);
                if (vo < v || (vo == v && io < ix)) { v = vo; ix = io; }
            }
            if (lm == 0) {
                int rl = wm * 64 + mt * 16 + l4 + h * 8;
                sv[rl][wn] = v; si[rl][wn] = ix;
            }
        }
    __syncthreads();
    if (tid < 128) {
        float bv = sv[tid][0]; int bi = si[tid][0];
#pragma unroll
        for (int t = 1; t < 4; t++) {
            float v = sv[tid][t]; int k2 = si[tid][t];
            if (v < bv || (v == bv && k2 < bi)) { bv = v; bi = k2; }
        }
        g_idx[row0 + tid] = bi;
        atomicAdd(&g_cnt[bi], 1);
    }
}

// ---------------- pre-pass kernels ----------------
__global__ void transpose_f16(const float* __restrict__ W, __half* __restrict__ WT,
                              int K, int N)
{
    __shared__ float t[32][33];
    int n0 = blockIdx.x * 32, k0 = blockIdx.y * 32;
    int tx = threadIdx.x, ty = threadIdx.y;
#pragma unroll
    for (int i = 0; i < 32; i += 8)
        t[ty + i][tx] = W[(size_t)(k0 + ty + i) * N + n0 + tx];
    __syncthreads();
#pragma unroll
    for (int i = 0; i < 32; i += 8)
        WT[(size_t)(n0 + ty + i) * K + k0 + tx] = __float2half_rn(t[tx][ty + i]);
}

__global__ void cvt_f16(const float* __restrict__ in, __half* __restrict__ out, int n4)
{
    int i = blockIdx.x * 256 + threadIdx.x;
    if (i < n4) {
        float4 v = ((const float4*)in)[i];
        ((__half2*)out)[2 * i]     = __floats2half2_rn(v.x, v.y);
        ((__half2*)out)[2 * i + 1] = __floats2half2_rn(v.z, v.w);
    }
}

__global__ void zero_cnt_kernel()
{
    int i = blockIdx.x * 256 + threadIdx.x;
    if (i < NK) g_cnt[i] = 0;
}

__global__ __launch_bounds__(256)
void cnorm_kernel(const __half* __restrict__ CBH)
{
    int warp = threadIdx.x >> 5, lane = threadIdx.x & 31;
    int code = blockIdx.x * 8 + warp;
    const __half* c = CBH + (size_t)code * NCD;
    float s = 0.f;
#pragma unroll
    for (int e = 0; e < 8; e++) { float v = __half2float(c[e * 32 + lane]); s += v * v; }
#pragma unroll
    for (int o = 16; o > 0; o >>= 1) s += __shfl_xor_sync(0xffffffffu, s, o);
    if (lane == 0) g_cnorm[code] = s;
}

__global__ __launch_bounds__(256)
void gather_loss_kernel(const __half* __restrict__ Z, const float* __restrict__ CB,
                        __half* __restrict__ HQ, __half* __restrict__ HQR)
{
    __shared__ float ws[8];
    int warp = threadIdx.x >> 5, lane = threadIdx.x & 31;
    int row  = blockIdx.x * 8 + warp;
    int id   = g_idx[row];
    const float*  q = CB + (size_t)id * NCD;
    const __half* z = Z + (size_t)row * NCD;
    __half* o   = HQ  + (size_t)row * NCD;
    __half* orl = HQR + (size_t)row * NCD;
    float s = 0.f;
#pragma unroll
    for (int e = 0; e < 8; e++) {
        int d = e * 32 + lane;
        float qq = q[d], zz = __half2float(z[d]);
        o[d]   = __float2half_rn(qq);
        orl[d] = __float2half_rn(fmaxf(qq, 0.f));
        float t = qq - zz;
        s += t * t;
    }
#pragma unroll
    for (int off = 16; off > 0; off >>= 1) s += __shfl_xor_sync(0xffffffffu, s, off);
    if (lane == 0) ws[warp] = s;
    __syncthreads();
    if (threadIdx.x == 0) {
        float t = 0.f;
#pragma unroll
        for (int w = 0; w < 8; w++) t += ws[w];
        g_losspart[blockIdx.x] = t;
    }
}

__global__ __launch_bounds__(256)
void finalize_kernel(float* __restrict__ out)
{
    __shared__ float red[256];
    int tid = threadIdx.x;

    float s = 0.f;
    for (int i = tid; i < NFLAT / 8; i += 256) s += g_losspart[i];
    red[tid] = s; __syncthreads();
    for (int o = 128; o > 0; o >>= 1) { if (tid < o) red[tid] += red[tid + o]; __syncthreads(); }
    float loss = red[0] * (1.25f / ((float)NB * (float)NEMB));
    __syncthreads();

    float e = 0.f;
    for (int i = tid; i < NK; i += 256) {
        float p = (float)g_cnt[i] * (1.0f / (float)NFLAT);
        e += p * logf(p + 1e-10f);
    }
    red[tid] = e; __syncthreads();
    for (int o = 128; o > 0; o >>= 1) { if (tid < o) red[tid] += red[tid + o]; __syncthreads(); }

    if (tid == 0) {
        out[0]            = loss;
        out[OUT_PERP_OFF] = expf(-red[0]);
    }
}

// ---------------- launch ----------------
extern "C" void kernel_launch(void* const* d_in, const int* in_sizes, int n_in,
                              void* d_out, int out_size)
{
    const float* x    = (const float*)d_in[0];
    const float* W1   = (const float*)d_in[1];
    const float* b1   = (const float*)d_in[2];
    const float* bn1g = (const float*)d_in[3];
    const float* bn1b = (const float*)d_in[4];
    const float* bn1m = (const float*)d_in[5];
    const float* bn1v = (const float*)d_in[6];
    const float* W2   = (const float*)d_in[7];
    const float* b2   = (const float*)d_in[8];
    const float* rbW  = (const float*)d_in[9];
    const float* rbb  = (const float*)d_in[10];
    const float* rbg  = (const float*)d_in[11];
    const float* rbbe = (const float*)d_in[12];
    const float* rbm  = (const float*)d_in[13];
    const float* rbv  = (const float*)d_in[14];
    const float* cb   = (const float*)d_in[15];
    const float* decW = (const float*)d_in[16];
    const float* decb = (const float*)d_in[17];
    float* out = (float*)d_out;

    __half *w1t, *w2t, *wt0, *wt1, *wt2, *wt3, *wt4, *wdt, *cbh;
    __half *ha, *har, *hb, *hbr, *gz;
    cudaGetSymbolAddress((void**)&w1t, g_w1t);
    cudaGetSymbolAddress((void**)&w2t, g_w2t);
    cudaGetSymbolAddress((void**)&wt0, g_wt0);
    cudaGetSymbolAddress((void**)&wt1, g_wt1);
    cudaGetSymbolAddress((void**)&wt2, g_wt2);
    cudaGetSymbolAddress((void**)&wt3, g_wt3);
    cudaGetSymbolAddress((void**)&wt4, g_wt4);
    cudaGetSymbolAddress((void**)&wdt, g_wdt);
    cudaGetSymbolAddress((void**)&cbh, g_cbh);
    cudaGetSymbolAddress((void**)&ha,  g_ha);
    cudaGetSymbolAddress((void**)&har, g_har);
    cudaGetSymbolAddress((void**)&hb,  g_hb);
    cudaGetSymbolAddress((void**)&hbr, g_hbr);
    cudaGetSymbolAddress((void**)&gz,  g_z);

    cudaFuncSetAttribute(gemm_h<EPI_BN_RELU, false, true >, cudaFuncAttributeMaxDynamicSharedMemorySize, SMEM_H32);
    cudaFuncSetAttribute(gemm_h<EPI_BIAS,    true,  false>, cudaFuncAttributeMaxDynamicSharedMemorySize, SMEM_H16);
    cudaFuncSetAttribute(gemm_h<EPI_RES,     true,  false>, cudaFuncAttributeMaxDynamicSharedMemorySize, SMEM_H16);
    cudaFuncSetAttribute(gemm_h<EPI_RES,     false, false>, cudaFuncAttributeMaxDynamicSharedMemorySize, SMEM_H16);
    cudaFuncSetAttribute(gemm_h<EPI_SIG,     false, false>, cudaFuncAttributeMaxDynamicSharedMemorySize, SMEM_H16);
    cudaFuncSetAttribute(vq_h, cudaFuncAttributeMaxDynamicSharedMemorySize, VQ_SMEM);

    const size_t WS = (size_t)NEMB * NEMB;
    dim3 tb(32, 8);
    dim3 blk(256);
    dim3 gE(NEMB / 256, NB / 128);
    dim3 gD(NIN / 256,  NB / 128);

    zero_cnt_kernel<<<(NK + 255) / 256, 256>>>();
    cvt_f16<<<(NK * NCD / 4 + 255) / 256, 256>>>(cb, cbh, NK * NCD / 4);
    cnorm_kernel<<<NK / 8, 256>>>(cbh);

    transpose_f16<<<dim3(NEMB / 32, NIN / 32),  tb>>>(W1, w1t, NIN, NEMB);
    transpose_f16<<<dim3(NEMB / 32, NEMB / 32), tb>>>(W2, w2t, NEMB, NEMB);
    transpose_f16<<<dim3(NEMB / 32, NEMB / 32), tb>>>(rbW + 0 * WS, wt0, NEMB, NEMB);
    transpose_f16<<<dim3(NEMB / 32, NEMB / 32), tb>>>(rbW + 1 * WS, wt1, NEMB, NEMB);
    transpose_f16<<<dim3(NEMB / 32, NEMB / 32), tb>>>(rbW + 2 * WS, wt2, NEMB, NEMB);
    transpose_f16<<<dim3(NEMB / 32, NEMB / 32), tb>>>(rbW + 3 * WS, wt3, NEMB, NEMB);
    transpose_f16<<<dim3(NEMB / 32, NEMB / 32), tb>>>(rbW + 4 * WS, wt4, NEMB, NEMB);
    transpose_f16<<<dim3(NIN / 32,  NEMB / 32), tb>>>(decW, wdt, NEMB, NIN);

    // encoder
    gemm_h<EPI_BN_RELU, false, true><<<gE, blk, SMEM_H32>>>(
        x, w1t, b1, bn1g, bn1b, bn1m, bn1v, nullptr, har, nullptr, NB, NEMB, NIN);
    gemm_h<EPI_BIAS, true, false><<<gE, blk, SMEM_H16>>>(
        har, w2t, b2, nullptr, nullptr, nullptr, nullptr, nullptr, hb, hbr, NB, NEMB, NEMB);
    gemm_h<EPI_RES, true, false><<<gE, blk, SMEM_H16>>>(
        hbr, wt0, rbb + 0 * NEMB, rbg + 0 * NEMB, rbbe + 0 * NEMB,
        rbm + 0 * NEMB, rbv + 0 * NEMB, hb, ha, har, NB, NEMB, NEMB);
    gemm_h<EPI_RES, false, false><<<gE, blk, SMEM_H16>>>(
        har, wt1, rbb + 1 * NEMB, rbg + 1 * NEMB, rbbe + 1 * NEMB,
        rbm + 1 * NEMB, rbv + 1 * NEMB, ha, gz, nullptr, NB, NEMB, NEMB);

    // vector quantizer
    vq_h<<<NFLAT / 128, blk, VQ_SMEM>>>(gz, cbh);
    gather_loss_kernel<<<NFLAT / 8, 256>>>(gz, cb, hb, hbr);
    finalize_kernel<<<1, 256>>>(out);

    // decoder
    gemm_h<EPI_RES, true, false><<<gE, blk, SMEM_H16>>>(
        hbr, wt2, rbb + 2 * NEMB, rbg + 2 * NEMB, rbbe + 2 * NEMB,
        rbm + 2 * NEMB, rbv + 2 * NEMB, hb, ha, har, NB, NEMB, NEMB);
    gemm_h<EPI_RES, true, false><<<gE, blk, SMEM_H16>>>(
        har, wt3, rbb + 3 * NEMB, rbg + 3 * NEMB, rbbe + 3 * NEMB,
        rbm + 3 * NEMB, rbv + 3 * NEMB, ha, hb, hbr, NB, NEMB, NEMB);
    gemm_h<EPI_RES, false, false><<<gE, blk, SMEM_H16>>>(
        hbr, wt4, rbb + 4 * NEMB, rbg + 4 * NEMB, rbbe + 4 * NEMB,
        rbm + 4 * NEMB, rbv + 4 * NEMB, hb, ha, nullptr, NB, NEMB, NEMB);
    gemm_h<EPI_SIG, false, false><<<gD, blk, SMEM_H16>>>(
        ha, wdt, decb, nullptr, nullptr, nullptr, nullptr, nullptr,
        out + 1, nullptr, NB, NIN, NEMB);
}

// round 8
// speedup vs baseline: 1.7982x; 1.0185x over previous
#include <cuda_runtime.h>
#include <cuda_fp16.h>
#include <math.h>
#include <stdint.h>

// ---------------- problem dims ----------------
#define NB    4096
#define NIN   8192
#define NEMB  1024
#define NK    4096
#define NCD   256
#define NFLAT 16384
#define OUT_PERP_OFF ((size_t)1 + (size_t)NB * (size_t)NIN)

#define EPI_BN_RELU 0
#define EPI_BIAS    1
#define EPI_RES     2
#define EPI_SIG     3

// ---------------- scratch (device globals) ----------------
__device__ __half g_w1t[(size_t)NIN * NEMB];
__device__ __half g_wts[(size_t)6 * NEMB * NEMB];   // [W2, rb0..rb4] transposed
__device__ __half g_wdt[(size_t)NIN * NEMB];
__device__ __half g_cbh[(size_t)NK * NCD];
__device__ __half g_ha [(size_t)NB * NEMB];
__device__ __half g_har[(size_t)NB * NEMB];
__device__ __half g_hb [(size_t)NB * NEMB];
__device__ __half g_hbr[(size_t)NB * NEMB];
__device__ __half g_z  [(size_t)NB * NEMB];
__device__ float  g_cnorm[NK];
__device__ int    g_idx[NFLAT];
__device__ int    g_cnt[NK];
__device__ float  g_losspart[NFLAT / 8];

// ---------------- small helpers ----------------
__device__ __forceinline__ void cp16(uint32_t dst, const void* src) {
    asm volatile("cp.async.cg.shared.global [%0], [%1], 16;" :: "r"(dst), "l"(src));
}
__device__ __forceinline__ void cp_commit() {
    asm volatile("cp.async.commit_group;");
}
template<int N>
__device__ __forceinline__ void cp_wait() {
    asm volatile("cp.async.wait_group %0;" :: "n"(N));
}
__device__ __forceinline__ void mma16(float* c, const uint32_t* a, const uint32_t* b) {
    asm volatile(
        "mma.sync.aligned.m16n8k16.row.col.f32.f16.f16.f32 "
        "{%0,%1,%2,%3},{%4,%5,%6,%7},{%8,%9},{%0,%1,%2,%3};"
        : "+f"(c[0]), "+f"(c[1]), "+f"(c[2]), "+f"(c[3])
        : "r"(a[0]), "r"(a[1]), "r"(a[2]), "r"(a[3]), "r"(b[0]), "r"(b[1]));
}
__device__ __forceinline__ void ldsm4(uint32_t& r0, uint32_t& r1, uint32_t& r2, uint32_t& r3,
                                      uint32_t addr) {
    asm volatile("ldmatrix.sync.aligned.m8n8.x4.shared.b16 {%0,%1,%2,%3}, [%4];"
                 : "=r"(r0), "=r"(r1), "=r"(r2), "=r"(r3) : "r"(addr));
}
__device__ __forceinline__ uint32_t pack_h2(float a, float b) {
    __half2 h = __floats2half2_rn(a, b);
    return *(uint32_t*)&h;
}

// ================= fp16 tensor-core GEMM (3-stage pipeline) =================
// block tile 128x256, BK=64, 8 warps (2x4), warp tile 64x64, m16n8k16, ldmatrix frags.
#define HBK   64
#define HA_STR 72
#define HAS   (128 * HA_STR)
#define FA_STR 68
#define FAS   (128 * FA_STR)
#define HBS   (256 * HA_STR)
#define SMEM_H16 (3 * (HAS * 2 + HBS * 2))   // 165888
#define SMEM_H32 (3 * (FAS * 4 + HBS * 2))   // 215040

template<int EPI, bool WRELU, bool A32>
__global__ void __launch_bounds__(256, 1)
gemm_h(const void* __restrict__ Ain, const __half* __restrict__ WT,
       const float* __restrict__ bias,
       const float* __restrict__ gamma, const float* __restrict__ beta,
       const float* __restrict__ mean,  const float* __restrict__ var,
       const __half* __restrict__ res,
       void* __restrict__ out0, __half* __restrict__ out1,
       int M, int N, int K)
{
    extern __shared__ char smem[];
    const int ASTG = A32 ? (FAS * 4) : (HAS * 2);   // bytes per A stage
    const int BSTG = HBS * 2;                        // bytes per B stage
    float*  Af = (float*)smem;
    __half* Bh = (__half*)(smem + 3 * ASTG);
    const uint32_t s_a = (uint32_t)__cvta_generic_to_shared(smem);
    const uint32_t s_b = (uint32_t)__cvta_generic_to_shared(Bh);

    const int tid  = threadIdx.x;
    const int lane = tid & 31;
    const int warp = tid >> 5;
    const int wm   = warp >> 2;
    const int wn   = warp & 3;
    const int row0 = blockIdx.y * 128;
    const int col0 = blockIdx.x * 256;
    const int l4   = lane >> 2;
    const int lm   = lane & 3;
    const int t8   = lane >> 3;
    const int jr   = lane & 7;

    uint32_t aBase[4], bBase[4];
#pragma unroll
    for (int mt = 0; mt < 4; mt++) {
        int r = wm * 64 + mt * 16 + ((t8 & 1) << 3) + jr;
        int c = (t8 >> 1) << 3;
        aBase[mt] = s_a + (uint32_t)(r * HA_STR + c) * 2;
    }
#pragma unroll
    for (int p = 0; p < 4; p++) {
        int r = wn * 64 + (2 * p + (t8 >> 1)) * 8 + jr;
        int c = (t8 & 1) << 3;
        bBase[p] = s_b + (uint32_t)(r * HA_STR + c) * 2;
    }

    float acc[4][8][4];
#pragma unroll
    for (int mt = 0; mt < 4; mt++)
#pragma unroll
        for (int nt = 0; nt < 8; nt++)
#pragma unroll
            for (int q = 0; q < 4; q++) acc[mt][nt][q] = 0.f;

    const int iters = K / HBK;

    auto loadA = [&](int s, int k0) {
        if (A32) {
            const float* A = (const float*)Ain;
#pragma unroll
            for (int i = 0; i < 8; i++) {
                int idx = i * 256 + tid;
                int r = idx >> 4, kc = (idx & 15) << 2;
                cp16(s_a + (uint32_t)(s * (FAS * 4)) + (uint32_t)(r * FA_STR + kc) * 4,
                     A + (size_t)(row0 + r) * K + k0 + kc);
            }
        } else {
            const __half* A = (const __half*)Ain;
#pragma unroll
            for (int i = 0; i < 4; i++) {
                int idx = i * 256 + tid;
                int r = idx >> 3, kc = (idx & 7) << 3;
                cp16(s_a + (uint32_t)(s * (HAS * 2)) + (uint32_t)(r * HA_STR + kc) * 2,
                     A + (size_t)(row0 + r) * K + k0 + kc);
            }
        }
    };
    auto loadB = [&](int s, int k0) {
#pragma unroll
        for (int i = 0; i < 8; i++) {
            int idx = i * 256 + tid;
            int n = idx >> 3, kc = (idx & 7) << 3;
            cp16(s_b + (uint32_t)(s * BSTG) + (uint32_t)(n * HA_STR + kc) * 2,
                 WT + (size_t)(col0 + n) * K + k0 + kc);
        }
    };

    // prologue: prefetch two stages
    loadA(0, 0); loadB(0, 0); cp_commit();
    loadA(1, HBK); loadB(1, HBK); cp_commit();

    for (int it = 0; it < iters; it++) {
        if (it + 1 < iters) cp_wait<1>(); else cp_wait<0>();
        __syncthreads();
        // stage (it+2)%3 was fully consumed at iter it-1 -> safe to refill now
        if (it + 2 < iters) {
            int ps = (it + 2) % 3;
            loadA(ps, (it + 2) * HBK);
            loadB(ps, (it + 2) * HBK);
            cp_commit();
        }

        const int s = it % 3;
        const float* af32 = Af + s * FAS;
        const uint32_t aOff = (uint32_t)(s * (HAS * 2));
        const uint32_t bOff = (uint32_t)(s * BSTG);
#pragma unroll
        for (int kk = 0; kk < HBK; kk += 16) {
            uint32_t af[4][4], bf[8][2];
#pragma unroll
            for (int mt = 0; mt < 4; mt++) {
                if (A32) {
                    int r = wm * 64 + mt * 16 + l4;
                    float2 v0 = *(const float2*)&af32[r * FA_STR + kk + 2 * lm];
                    float2 v1 = *(const float2*)&af32[(r + 8) * FA_STR + kk + 2 * lm];
                    float2 v2 = *(const float2*)&af32[r * FA_STR + kk + 8 + 2 * lm];
                    float2 v3 = *(const float2*)&af32[(r + 8) * FA_STR + kk + 8 + 2 * lm];
                    af[mt][0] = pack_h2(v0.x, v0.y);
                    af[mt][1] = pack_h2(v1.x, v1.y);
                    af[mt][2] = pack_h2(v2.x, v2.y);
                    af[mt][3] = pack_h2(v3.x, v3.y);
                } else {
                    ldsm4(af[mt][0], af[mt][1], af[mt][2], af[mt][3],
                          aBase[mt] + aOff + (uint32_t)kk * 2);
                }
            }
#pragma unroll
            for (int p = 0; p < 4; p++)
                ldsm4(bf[2 * p][0], bf[2 * p][1], bf[2 * p + 1][0], bf[2 * p + 1][1],
                      bBase[p] + bOff + (uint32_t)kk * 2);
#pragma unroll
            for (int mt = 0; mt < 4; mt++)
#pragma unroll
                for (int nt = 0; nt < 8; nt++)
                    mma16(acc[mt][nt], af[mt], bf[nt]);
        }
    }

    // ---- epilogue ----
#pragma unroll
    for (int nt = 0; nt < 8; nt++) {
        int c = col0 + wn * 64 + nt * 8 + (lm << 1);
        float b0 = bias[c], b1 = bias[c + 1];
        float g0 = 0.f, g1 = 0.f, be0 = 0.f, be1 = 0.f, m0 = 0.f, m1 = 0.f;
        if (EPI == EPI_BN_RELU || EPI == EPI_RES) {
            g0 = gamma[c]     * rsqrtf(var[c]     + 1e-5f);
            g1 = gamma[c + 1] * rsqrtf(var[c + 1] + 1e-5f);
            be0 = beta[c]; be1 = beta[c + 1];
            m0 = mean[c]; m1 = mean[c + 1];
        }
#pragma unroll
        for (int mt = 0; mt < 4; mt++) {
#pragma unroll
            for (int h = 0; h < 2; h++) {
                int r = row0 + wm * 64 + mt * 16 + l4 + h * 8;
                size_t off = (size_t)r * N + c;
                float x0 = acc[mt][nt][h * 2 + 0] + b0;
                float x1 = acc[mt][nt][h * 2 + 1] + b1;
                if (EPI == EPI_SIG) {
                    float* o = (float*)out0;
                    o[off]     = 1.f / (1.f + expf(-x0));
                    o[off + 1] = 1.f / (1.f + expf(-x1));
                    continue;
                }
                if (EPI == EPI_BN_RELU) {
                    x0 = fmaxf((x0 - m0) * g0 + be0, 0.f);
                    x1 = fmaxf((x1 - m1) * g1 + be1, 0.f);
                } else if (EPI == EPI_RES) {
                    __half2 rv = *(const __half2*)(res + off);
                    x0 = (x0 - m0) * g0 + be0 + __half2float(rv.x);
                    x1 = (x1 - m1) * g1 + be1 + __half2float(rv.y);
                }
                __half2 ov; ov.x = __float2half_rn(x0); ov.y = __float2half_rn(x1);
                *(__half2*)((__half*)out0 + off) = ov;
                if (WRELU) {
                    __half2 rw;
                    rw.x = __float2half_rn(fmaxf(x0, 0.f));
                    rw.y = __float2half_rn(fmaxf(x1, 0.f));
                    *(__half2*)(out1 + off) = rw;
                }
            }
        }
    }
}

// ================= VQ: fp16 mma distances + fused argmin (3-stage B) =================
#define AZ_STR 264
#define VQ_SMEM (128 * AZ_STR * 2 + 3 * HBS * 2)   // 67584 + 110592 = 178176

__global__ void __launch_bounds__(256, 1)
vq_h(const __half* __restrict__ Z, const __half* __restrict__ CBH)
{
    extern __shared__ char smem[];
    __half* Az = (__half*)smem;
    __half* Bh = (__half*)(smem + 128 * AZ_STR * 2);
    const uint32_t s_az = (uint32_t)__cvta_generic_to_shared(Az);
    const uint32_t s_b  = (uint32_t)__cvta_generic_to_shared(Bh);
    __shared__ float sv[128][4];
    __shared__ int   si[128][4];

    const int tid  = threadIdx.x;
    const int lane = tid & 31;
    const int warp = tid >> 5;
    const int wm   = warp >> 2;
    const int wn   = warp & 3;
    const int row0 = blockIdx.x * 128;
    const int l4   = lane >> 2;
    const int lm   = lane & 3;
    const int t8   = lane >> 3;
    const int jr   = lane & 7;

    uint32_t aBase[4], bBase[4];
#pragma unroll
    for (int mt = 0; mt < 4; mt++) {
        int r = wm * 64 + mt * 16 + ((t8 & 1) << 3) + jr;
        int c = (t8 >> 1) << 3;
        aBase[mt] = s_az + (uint32_t)(r * AZ_STR + c) * 2;
    }
#pragma unroll
    for (int p = 0; p < 4; p++) {
        int r = wn * 64 + (2 * p + (t8 >> 1)) * 8 + jr;
        int c = (t8 & 1) << 3;
        bBase[p] = s_b + (uint32_t)(r * HA_STR + c) * 2;
    }

    auto loadB = [&](int s, int chunk) {
        int ct = chunk >> 2, k0 = (chunk & 3) * 64;
#pragma unroll
        for (int i = 0; i < 8; i++) {
            int idx = i * 256 + tid;
            int code = idx >> 3, kc = (idx & 7) << 3;
            cp16(s_b + (uint32_t)(s * (HBS * 2)) + (uint32_t)(code * HA_STR + kc) * 2,
                 CBH + (size_t)(ct * 256 + code) * NCD + k0 + kc);
        }
    };

    // resident z tile + first B stage -> group 0; second B stage -> group 1
#pragma unroll
    for (int i = 0; i < 16; i++) {
        int idx = i * 256 + tid;
        int r = idx >> 5, kc = (idx & 31) << 3;
        cp16(s_az + (uint32_t)(r * AZ_STR + kc) * 2,
             Z + (size_t)(row0 + r) * NCD + kc);
    }
    loadB(0, 0); cp_commit();
    loadB(1, 1); cp_commit();

    float minv[4][2];
    int   mini[4][2];
#pragma unroll
    for (int mt = 0; mt < 4; mt++)
#pragma unroll
        for (int h = 0; h < 2; h++) { minv[mt][h] = 3.4e38f; mini[mt][h] = 0; }

    float acc[4][8][4];
#pragma unroll
    for (int mt = 0; mt < 4; mt++)
#pragma unroll
        for (int nt = 0; nt < 8; nt++)
#pragma unroll
            for (int q = 0; q < 4; q++) acc[mt][nt][q] = 0.f;

    for (int c = 0; c < 64; c++) {
        if (c + 1 < 64) cp_wait<1>(); else cp_wait<0>();
        __syncthreads();
        if (c + 2 < 64) { loadB((c + 2) % 3, c + 2); cp_commit(); }

        const int s = c % 3;
        const uint32_t bOff = (uint32_t)(s * (HBS * 2));
        const int kg = (c & 3) * 64;
#pragma unroll
        for (int kk = 0; kk < 64; kk += 16) {
            uint32_t af[4][4], bf[8][2];
#pragma unroll
            for (int mt = 0; mt < 4; mt++)
                ldsm4(af[mt][0], af[mt][1], af[mt][2], af[mt][3],
                      aBase[mt] + (uint32_t)(kg + kk) * 2);
#pragma unroll
            for (int p = 0; p < 4; p++)
                ldsm4(bf[2 * p][0], bf[2 * p][1], bf[2 * p + 1][0], bf[2 * p + 1][1],
                      bBase[p] + bOff + (uint32_t)kk * 2);
#pragma unroll
            for (int mt = 0; mt < 4; mt++)
#pragma unroll
                for (int nt = 0; nt < 8; nt++)
                    mma16(acc[mt][nt], af[mt], bf[nt]);
        }

        if ((c & 3) == 3) {
            int ct = (c >> 2) * 256;
#pragma unroll
            for (int nt = 0; nt < 8; nt++) {
                int code = ct + wn * 64 + nt * 8 + (lm << 1);
                float cn0 = g_cnorm[code], cn1 = g_cnorm[code + 1];
#pragma unroll
                for (int mt = 0; mt < 4; mt++)
#pragma unroll
                    for (int h = 0; h < 2; h++) {
                        float d0 = cn0 - 2.f * acc[mt][nt][h * 2 + 0];
                        float d1 = cn1 - 2.f * acc[mt][nt][h * 2 + 1];
                        if (d0 < minv[mt][h]) { minv[mt][h] = d0; mini[mt][h] = code; }
                        if (d1 < minv[mt][h]) { minv[mt][h] = d1; mini[mt][h] = code + 1; }
                        acc[mt][nt][h * 2 + 0] = 0.f;
                        acc[mt][nt][h * 2 + 1] = 0.f;
                    }
            }
        }
    }

#pragma unroll
    for (int mt = 0; mt < 4; mt++)
#pragma unroll
        for (int h = 0; h < 2; h++) {
            float v = minv[mt][h]; int ix = mini[mt][h];
#pragma unroll
            for (int o = 1; o <= 2; o <<= 1) {
                float vo = __shfl_xor_sync(0xffffffffu, v, o);
                int   io = __shfl_xor_sync(0xffffffffu, ix, o);
                if (vo < v || (vo == v && io < ix)) { v = vo; ix = io; }
            }
            if (lm == 0) {
                int rl = wm * 64 + mt * 16 + l4 + h * 8;
                sv[rl][wn] = v; si[rl][wn] = ix;
            }
        }
    __syncthreads();
    if (tid < 128) {
        float bv = sv[tid][0]; int bi = si[tid][0];
#pragma unroll
        for (int t = 1; t < 4; t++) {
            float v = sv[tid][t]; int k2 = si[tid][t];
            if (v < bv || (v == bv && k2 < bi)) { bv = v; bi = k2; }
        }
        g_idx[row0 + tid] = bi;
        atomicAdd(&g_cnt[bi], 1);
    }
}

// ---------------- pre-pass kernels ----------------
__global__ void transpose_f16(const float* __restrict__ W, __half* __restrict__ WT,
                              int K, int N)
{
    __shared__ float t[32][33];
    int n0 = blockIdx.x * 32, k0 = blockIdx.y * 32;
    int tx = threadIdx.x, ty = threadIdx.y;
#pragma unroll
    for (int i = 0; i < 32; i += 8)
        t[ty + i][tx] = W[(size_t)(k0 + ty + i) * N + n0 + tx];
    __syncthreads();
#pragma unroll
    for (int i = 0; i < 32; i += 8)
        WT[(size_t)(n0 + ty + i) * K + k0 + tx] = __float2half_rn(t[tx][ty + i]);
}

// batched square transpose: z=0 -> W2, z=1..5 -> rbW[z-1]; dst = g_wts + z*WS
__global__ void transpose_sq6(const float* __restrict__ W2, const float* __restrict__ rbW,
                              __half* __restrict__ dst)
{
    __shared__ float t[32][33];
    int z = blockIdx.z;
    const float* src = (z == 0) ? W2 : rbW + (size_t)(z - 1) * NEMB * NEMB;
    __half* out = dst + (size_t)z * NEMB * NEMB;
    int n0 = blockIdx.x * 32, k0 = blockIdx.y * 32;
    int tx = threadIdx.x, ty = threadIdx.y;
#pragma unroll
    for (int i = 0; i < 32; i += 8)
        t[ty + i][tx] = src[(size_t)(k0 + ty + i) * NEMB + n0 + tx];
    __syncthreads();
#pragma unroll
    for (int i = 0; i < 32; i += 8)
        out[(size_t)(n0 + ty + i) * NEMB + k0 + tx] = __float2half_rn(t[tx][ty + i]);
}

__global__ void cvt_f16(const float* __restrict__ in, __half* __restrict__ out, int n4)
{
    int i = blockIdx.x * 256 + threadIdx.x;
    if (i < n4) {
        float4 v = ((const float4*)in)[i];
        ((__half2*)out)[2 * i]     = __floats2half2_rn(v.x, v.y);
        ((__half2*)out)[2 * i + 1] = __floats2half2_rn(v.z, v.w);
    }
}

__global__ void zero_cnt_kernel()
{
    int i = blockIdx.x * 256 + threadIdx.x;
    if (i < NK) g_cnt[i] = 0;
}

__global__ __launch_bounds__(256)
void cnorm_kernel(const __half* __restrict__ CBH)
{
    int warp = threadIdx.x >> 5, lane = threadIdx.x & 31;
    int code = blockIdx.x * 8 + warp;
    const __half* c = CBH + (size_t)code * NCD;
    float s = 0.f;
#pragma unroll
    for (int e = 0; e < 8; e++) { float v = __half2float(c[e * 32 + lane]); s += v * v; }
#pragma unroll
    for (int o = 16; o > 0; o >>= 1) s += __shfl_xor_sync(0xffffffffu, s, o);
    if (lane == 0) g_cnorm[code] = s;
}

__global__ __launch_bounds__(256)
void gather_loss_kernel(const __half* __restrict__ Z, const float* __restrict__ CB,
                        __half* __restrict__ HQ, __half* __restrict__ HQR)
{
    __shared__ float ws[8];
    int warp = threadIdx.x >> 5, lane = threadIdx.x & 31;
    int row  = blockIdx.x * 8 + warp;
    int id   = g_idx[row];
    const float*  q = CB + (size_t)id * NCD;
    const __half* z = Z + (size_t)row * NCD;
    __half* o   = HQ  + (size_t)row * NCD;
    __half* orl = HQR + (size_t)row * NCD;
    float s = 0.f;
#pragma unroll
    for (int e = 0; e < 8; e++) {
        int d = e * 32 + lane;
        float qq = q[d], zz = __half2float(z[d]);
        o[d]   = __float2half_rn(qq);
        orl[d] = __float2half_rn(fmaxf(qq, 0.f));
        float t = qq - zz;
        s += t * t;
    }
#pragma unroll
    for (int off = 16; off > 0; off >>= 1) s += __shfl_xor_sync(0xffffffffu, s, off);
    if (lane == 0) ws[warp] = s;
    __syncthreads();
    if (threadIdx.x == 0) {
        float t = 0.f;
#pragma unroll
        for (int w = 0; w < 8; w++) t += ws[w];
        g_losspart[blockIdx.x] = t;
    }
}

__global__ __launch_bounds__(256)
void finalize_kernel(float* __restrict__ out)
{
    __shared__ float red[256];
    int tid = threadIdx.x;

    float s = 0.f;
    for (int i = tid; i < NFLAT / 8; i += 256) s += g_losspart[i];
    red[tid] = s; __syncthreads();
    for (int o = 128; o > 0; o >>= 1) { if (tid < o) red[tid] += red[tid + o]; __syncthreads(); }
    float loss = red[0] * (1.25f / ((float)NB * (float)NEMB));
    __syncthreads();

    float e = 0.f;
    for (int i = tid; i < NK; i += 256) {
        float p = (float)g_cnt[i] * (1.0f / (float)NFLAT);
        e += p * logf(p + 1e-10f);
    }
    red[tid] = e; __syncthreads();
    for (int o = 128; o > 0; o >>= 1) { if (tid < o) red[tid] += red[tid + o]; __syncthreads(); }

    if (tid == 0) {
        out[0]            = loss;
        out[OUT_PERP_OFF] = expf(-red[0]);
    }
}

// ---------------- launch ----------------
extern "C" void kernel_launch(void* const* d_in, const int* in_sizes, int n_in,
                              void* d_out, int out_size)
{
    const float* x    = (const float*)d_in[0];
    const float* W1   = (const float*)d_in[1];
    const float* b1   = (const float*)d_in[2];
    const float* bn1g = (const float*)d_in[3];
    const float* bn1b = (const float*)d_in[4];
    const float* bn1m = (const float*)d_in[5];
    const float* bn1v = (const float*)d_in[6];
    const float* W2   = (const float*)d_in[7];
    const float* b2   = (const float*)d_in[8];
    const float* rbW  = (const float*)d_in[9];
    const float* rbb  = (const float*)d_in[10];
    const float* rbg  = (const float*)d_in[11];
    const float* rbbe = (const float*)d_in[12];
    const float* rbm  = (const float*)d_in[13];
    const float* rbv  = (const float*)d_in[14];
    const float* cb   = (const float*)d_in[15];
    const float* decW = (const float*)d_in[16];
    const float* decb = (const float*)d_in[17];
    float* out = (float*)d_out;

    __half *w1t, *wts, *wdt, *cbh, *ha, *har, *hb, *hbr, *gz;
    cudaGetSymbolAddress((void**)&w1t, g_w1t);
    cudaGetSymbolAddress((void**)&wts, g_wts);
    cudaGetSymbolAddress((void**)&wdt, g_wdt);
    cudaGetSymbolAddress((void**)&cbh, g_cbh);
    cudaGetSymbolAddress((void**)&ha,  g_ha);
    cudaGetSymbolAddress((void**)&har, g_har);
    cudaGetSymbolAddress((void**)&hb,  g_hb);
    cudaGetSymbolAddress((void**)&hbr, g_hbr);
    cudaGetSymbolAddress((void**)&gz,  g_z);

    cudaFuncSetAttribute(gemm_h<EPI_BN_RELU, false, true >, cudaFuncAttributeMaxDynamicSharedMemorySize, SMEM_H32);
    cudaFuncSetAttribute(gemm_h<EPI_BIAS,    true,  false>, cudaFuncAttributeMaxDynamicSharedMemorySize, SMEM_H16);
    cudaFuncSetAttribute(gemm_h<EPI_RES,     true,  false>, cudaFuncAttributeMaxDynamicSharedMemorySize, SMEM_H16);
    cudaFuncSetAttribute(gemm_h<EPI_RES,     false, false>, cudaFuncAttributeMaxDynamicSharedMemorySize, SMEM_H16);
    cudaFuncSetAttribute(gemm_h<EPI_SIG,     false, false>, cudaFuncAttributeMaxDynamicSharedMemorySize, SMEM_H16);
    cudaFuncSetAttribute(vq_h, cudaFuncAttributeMaxDynamicSharedMemorySize, VQ_SMEM);

    const size_t WS = (size_t)NEMB * NEMB;
    dim3 tb(32, 8);
    dim3 blk(256);
    dim3 gE(NEMB / 256, NB / 128);
    dim3 gD(NIN / 256,  NB / 128);

    zero_cnt_kernel<<<(NK + 255) / 256, 256>>>();
    cvt_f16<<<(NK * NCD / 4 + 255) / 256, 256>>>(cb, cbh, NK * NCD / 4);
    cnorm_kernel<<<NK / 8, 256>>>(cbh);

    transpose_f16<<<dim3(NEMB / 32, NIN / 32),  tb>>>(W1, w1t, NIN, NEMB);
    transpose_sq6<<<dim3(32, 32, 6), tb>>>(W2, rbW, wts);
    transpose_f16<<<dim3(NIN / 32,  NEMB / 32), tb>>>(decW, wdt, NEMB, NIN);

    __half* w2t = wts + 0 * WS;
    __half* wt0 = wts + 1 * WS;
    __half* wt1 = wts + 2 * WS;
    __half* wt2 = wts + 3 * WS;
    __half* wt3 = wts + 4 * WS;
    __half* wt4 = wts + 5 * WS;

    // encoder
    gemm_h<EPI_BN_RELU, false, true><<<gE, blk, SMEM_H32>>>(
        x, w1t, b1, bn1g, bn1b, bn1m, bn1v, nullptr, har, nullptr, NB, NEMB, NIN);
    gemm_h<EPI_BIAS, true, false><<<gE, blk, SMEM_H16>>>(
        har, w2t, b2, nullptr, nullptr, nullptr, nullptr, nullptr, hb, hbr, NB, NEMB, NEMB);
    gemm_h<EPI_RES, true, false><<<gE, blk, SMEM_H16>>>(
        hbr, wt0, rbb + 0 * NEMB, rbg + 0 * NEMB, rbbe + 0 * NEMB,
        rbm + 0 * NEMB, rbv + 0 * NEMB, hb, ha, har, NB, NEMB, NEMB);
    gemm_h<EPI_RES, false, false><<<gE, blk, SMEM_H16>>>(
        har, wt1, rbb + 1 * NEMB, rbg + 1 * NEMB, rbbe + 1 * NEMB,
        rbm + 1 * NEMB, rbv + 1 * NEMB, ha, gz, nullptr, NB, NEMB, NEMB);

    // vector quantizer
    vq_h<<<NFLAT / 128, blk, VQ_SMEM>>>(gz, cbh);
    gather_loss_kernel<<<NFLAT / 8, 256>>>(gz, cb, hb, hbr);
    finalize_kernel<<<1, 256>>>(out);

    // decoder
    gemm_h<EPI_RES, true, false><<<gE, blk, SMEM_H16>>>(
        hbr, wt2, rbb + 2 * NEMB, rbg + 2 * NEMB, rbbe + 2 * NEMB,
        rbm + 2 * NEMB, rbv + 2 * NEMB, hb, ha, har, NB, NEMB, NEMB);
    gemm_h<EPI_RES, true, false><<<gE, blk, SMEM_H16>>>(
        har, wt3, rbb + 3 * NEMB, rbg + 3 * NEMB, rbbe + 3 * NEMB,
        rbm + 3 * NEMB, rbv + 3 * NEMB, ha, hb, hbr, NB, NEMB, NEMB);
    gemm_h<EPI_RES, false, false><<<gE, blk, SMEM_H16>>>(
        hbr, wt4, rbb + 4 * NEMB, rbg + 4 * NEMB, rbbe + 4 * NEMB,
        rbm + 4 * NEMB, rbv + 4 * NEMB, hb, ha, nullptr, NB, NEMB, NEMB);
    gemm_h<EPI_SIG, false, false><<<gD, blk, SMEM_H16>>>(
        ha, wdt, decb, nullptr, nullptr, nullptr, nullptr, nullptr,
        out + 1, nullptr, NB, NIN, NEMB);
}

// round 10
// speedup vs baseline: 1.8252x; 1.0150x over previous
#include <cuda_runtime.h>
#include <cuda_fp16.h>
#include <cuda_fp8.h>
#include <math.h>
#include <stdint.h>

// ---------------- problem dims ----------------
#define NB    4096
#define NIN   8192
#define NEMB  1024
#define NK    4096
#define NCD   256
#define NFLAT 16384
#define OUT_PERP_OFF ((size_t)1 + (size_t)NB * (size_t)NIN)

#define EPI_BN_RELU 0
#define EPI_BIAS    1
#define EPI_RES     2
#define EPI_SIG     3

#define QSCALE     4096.0f
#define QSCALE_INV 0.000244140625f

// ---------------- scratch (device globals) ----------------
__device__ __half  g_w1t[(size_t)NIN * NEMB];
__device__ __half  g_wts[(size_t)3 * NEMB * NEMB];    // W2, rb0, rb1 (fp16, [n][k])
__device__ uint8_t g_wq [(size_t)3 * NEMB * NEMB];    // rb2, rb3, rb4 (e4m3, [n][k])
__device__ uint8_t g_wqd[(size_t)NIN * NEMB];         // decW (e4m3, [n][k])
__device__ __half  g_cbh[(size_t)NK * NCD];
__device__ __half  g_ha [(size_t)NB * NEMB];
__device__ __half  g_har[(size_t)NB * NEMB];
__device__ __half  g_hb [(size_t)NB * NEMB];
__device__ __half  g_hbr[(size_t)NB * NEMB];
__device__ __half  g_z  [(size_t)NB * NEMB];
__device__ uint8_t g_q1 [(size_t)NB * NEMB];
__device__ uint8_t g_q2 [(size_t)NB * NEMB];
__device__ float   g_cnorm[NK];
__device__ int     g_idx[NFLAT];
__device__ int     g_cnt[NK];
__device__ float   g_losspart[NFLAT / 8];

// ---------------- helpers ----------------
__device__ __forceinline__ void cp16(uint32_t dst, const void* src) {
    asm volatile("cp.async.cg.shared.global [%0], [%1], 16;" :: "r"(dst), "l"(src));
}
__device__ __forceinline__ void cp_commit() {
    asm volatile("cp.async.commit_group;");
}
template<int N>
__device__ __forceinline__ void cp_wait() {
    asm volatile("cp.async.wait_group %0;" :: "n"(N));
}
__device__ __forceinline__ void mma16(float* c, const uint32_t* a, const uint32_t* b) {
    asm volatile(
        "mma.sync.aligned.m16n8k16.row.col.f32.f16.f16.f32 "
        "{%0,%1,%2,%3},{%4,%5,%6,%7},{%8,%9},{%0,%1,%2,%3};"
        : "+f"(c[0]), "+f"(c[1]), "+f"(c[2]), "+f"(c[3])
        : "r"(a[0]), "r"(a[1]), "r"(a[2]), "r"(a[3]), "r"(b[0]), "r"(b[1]));
}
__device__ __forceinline__ void mmaq(float* c, const uint32_t* a, const uint32_t* b) {
    asm volatile(
        "mma.sync.aligned.m16n8k32.row.col.f32.e4m3.e4m3.f32 "
        "{%0,%1,%2,%3},{%4,%5,%6,%7},{%8,%9},{%0,%1,%2,%3};"
        : "+f"(c[0]), "+f"(c[1]), "+f"(c[2]), "+f"(c[3])
        : "r"(a[0]), "r"(a[1]), "r"(a[2]), "r"(a[3]), "r"(b[0]), "r"(b[1]));
}
__device__ __forceinline__ void ldsm4(uint32_t& r0, uint32_t& r1, uint32_t& r2, uint32_t& r3,
                                      uint32_t addr) {
    asm volatile("ldmatrix.sync.aligned.m8n8.x4.shared.b16 {%0,%1,%2,%3}, [%4];"
                 : "=r"(r0), "=r"(r1), "=r"(r2), "=r"(r3) : "r"(addr));
}
__device__ __forceinline__ uint32_t pack_h2(float a, float b) {
    __half2 h = __floats2half2_rn(a, b);
    return *(uint32_t*)&h;
}
// pack two floats into e4m3x2: lo -> byte0, hi -> byte1
__device__ __forceinline__ uint16_t pack_q2(float lo, float hi) {
    uint16_t r;
    asm("cvt.rn.satfinite.e4m3x2.f32 %0, %1, %2;" : "=h"(r) : "f"(hi), "f"(lo));
    return r;
}

// ================= fp16 tensor-core GEMM (R8 proven: 3-stage, ldmatrix) =================
#define HBK   64
#define HA_STR 72
#define HAS   (128 * HA_STR)
#define FA_STR 68
#define FAS   (128 * FA_STR)
#define HBS   (256 * HA_STR)
#define SMEM_H16 (3 * (HAS * 2 + HBS * 2))
#define SMEM_H32 (3 * (FAS * 4 + HBS * 2))

template<int EPI, bool WRELU, bool A32>
__global__ void __launch_bounds__(256, 1)
gemm_h(const void* __restrict__ Ain, const __half* __restrict__ WT,
       const float* __restrict__ bias,
       const float* __restrict__ gamma, const float* __restrict__ beta,
       const float* __restrict__ mean,  const float* __restrict__ var,
       const __half* __restrict__ res,
       void* __restrict__ out0, __half* __restrict__ out1,
       int M, int N, int K)
{
    extern __shared__ char smem[];
    const int ASTG = A32 ? (FAS * 4) : (HAS * 2);
    const int BSTG = HBS * 2;
    float* Af = (float*)smem;
    __half* Bh = (__half*)(smem + 3 * ASTG);
    const uint32_t s_a = (uint32_t)__cvta_generic_to_shared(smem);
    const uint32_t s_b = (uint32_t)__cvta_generic_to_shared(Bh);

    const int tid  = threadIdx.x;
    const int lane = tid & 31;
    const int warp = tid >> 5;
    const int wm   = warp >> 2;
    const int wn   = warp & 3;
    const int row0 = blockIdx.y * 128;
    const int col0 = blockIdx.x * 256;
    const int l4   = lane >> 2;
    const int lm   = lane & 3;
    const int t8   = lane >> 3;
    const int jr   = lane & 7;

    uint32_t aBase[4], bBase[4];
#pragma unroll
    for (int mt = 0; mt < 4; mt++) {
        int r = wm * 64 + mt * 16 + ((t8 & 1) << 3) + jr;
        int c = (t8 >> 1) << 3;
        aBase[mt] = s_a + (uint32_t)(r * HA_STR + c) * 2;
    }
#pragma unroll
    for (int p = 0; p < 4; p++) {
        int r = wn * 64 + (2 * p + (t8 >> 1)) * 8 + jr;
        int c = (t8 & 1) << 3;
        bBase[p] = s_b + (uint32_t)(r * HA_STR + c) * 2;
    }

    float acc[4][8][4];
#pragma unroll
    for (int mt = 0; mt < 4; mt++)
#pragma unroll
        for (int nt = 0; nt < 8; nt++)
#pragma unroll
            for (int q = 0; q < 4; q++) acc[mt][nt][q] = 0.f;

    const int iters = K / HBK;

    auto loadA = [&](int s, int k0) {
        if (A32) {
            const float* A = (const float*)Ain;
#pragma unroll
            for (int i = 0; i < 8; i++) {
                int idx = i * 256 + tid;
                int r = idx >> 4, kc = (idx & 15) << 2;
                cp16(s_a + (uint32_t)(s * (FAS * 4)) + (uint32_t)(r * FA_STR + kc) * 4,
                     A + (size_t)(row0 + r) * K + k0 + kc);
            }
        } else {
            const __half* A = (const __half*)Ain;
#pragma unroll
            for (int i = 0; i < 4; i++) {
                int idx = i * 256 + tid;
                int r = idx >> 3, kc = (idx & 7) << 3;
                cp16(s_a + (uint32_t)(s * (HAS * 2)) + (uint32_t)(r * HA_STR + kc) * 2,
                     A + (size_t)(row0 + r) * K + k0 + kc);
            }
        }
    };
    auto loadB = [&](int s, int k0) {
#pragma unroll
        for (int i = 0; i < 8; i++) {
            int idx = i * 256 + tid;
            int n = idx >> 3, kc = (idx & 7) << 3;
            cp16(s_b + (uint32_t)(s * BSTG) + (uint32_t)(n * HA_STR + kc) * 2,
                 WT + (size_t)(col0 + n) * K + k0 + kc);
        }
    };

    loadA(0, 0); loadB(0, 0); cp_commit();
    loadA(1, HBK); loadB(1, HBK); cp_commit();

    for (int it = 0; it < iters; it++) {
        if (it + 1 < iters) cp_wait<1>(); else cp_wait<0>();
        __syncthreads();
        if (it + 2 < iters) {
            int ps = (it + 2) % 3;
            loadA(ps, (it + 2) * HBK);
            loadB(ps, (it + 2) * HBK);
            cp_commit();
        }

        const int s = it % 3;
        const float* af32 = Af + s * FAS;
        const uint32_t aOff = (uint32_t)(s * (HAS * 2));
        const uint32_t bOff = (uint32_t)(s * BSTG);
#pragma unroll
        for (int kk = 0; kk < HBK; kk += 16) {
            uint32_t af[4][4], bf[8][2];
#pragma unroll
            for (int mt = 0; mt < 4; mt++) {
                if (A32) {
                    int r = wm * 64 + mt * 16 + l4;
                    float2 v0 = *(const float2*)&af32[r * FA_STR + kk + 2 * lm];
                    float2 v1 = *(const float2*)&af32[(r + 8) * FA_STR + kk + 2 * lm];
                    float2 v2 = *(const float2*)&af32[r * FA_STR + kk + 8 + 2 * lm];
                    float2 v3 = *(const float2*)&af32[(r + 8) * FA_STR + kk + 8 + 2 * lm];
                    af[mt][0] = pack_h2(v0.x, v0.y);
                    af[mt][1] = pack_h2(v1.x, v1.y);
                    af[mt][2] = pack_h2(v2.x, v2.y);
                    af[mt][3] = pack_h2(v3.x, v3.y);
                } else {
                    ldsm4(af[mt][0], af[mt][1], af[mt][2], af[mt][3],
                          aBase[mt] + aOff + (uint32_t)kk * 2);
                }
            }
#pragma unroll
            for (int p = 0; p < 4; p++)
                ldsm4(bf[2 * p][0], bf[2 * p][1], bf[2 * p + 1][0], bf[2 * p + 1][1],
                      bBase[p] + bOff + (uint32_t)kk * 2);
#pragma unroll
            for (int mt = 0; mt < 4; mt++)
#pragma unroll
                for (int nt = 0; nt < 8; nt++)
                    mma16(acc[mt][nt], af[mt], bf[nt]);
        }
    }

    // ---- epilogue ----
#pragma unroll
    for (int nt = 0; nt < 8; nt++) {
        int c = col0 + wn * 64 + nt * 8 + (lm << 1);
        float b0 = bias[c], b1 = bias[c + 1];
        float g0 = 0.f, g1 = 0.f, be0 = 0.f, be1 = 0.f, m0 = 0.f, m1 = 0.f;
        if (EPI == EPI_BN_RELU || EPI == EPI_RES) {
            g0 = gamma[c]     * rsqrtf(var[c]     + 1e-5f);
            g1 = gamma[c + 1] * rsqrtf(var[c + 1] + 1e-5f);
            be0 = beta[c]; be1 = beta[c + 1];
            m0 = mean[c]; m1 = mean[c + 1];
        }
#pragma unroll
        for (int mt = 0; mt < 4; mt++) {
#pragma unroll
            for (int h = 0; h < 2; h++) {
                int r = row0 + wm * 64 + mt * 16 + l4 + h * 8;
                size_t off = (size_t)r * N + c;
                float x0 = acc[mt][nt][h * 2 + 0] + b0;
                float x1 = acc[mt][nt][h * 2 + 1] + b1;
                if (EPI == EPI_BN_RELU) {
                    x0 = fmaxf((x0 - m0) * g0 + be0, 0.f);
                    x1 = fmaxf((x1 - m1) * g1 + be1, 0.f);
                } else if (EPI == EPI_RES) {
                    __half2 rv = *(const __half2*)(res + off);
                    x0 = (x0 - m0) * g0 + be0 + __half2float(rv.x);
                    x1 = (x1 - m1) * g1 + be1 + __half2float(rv.y);
                }
                __half2 ov; ov.x = __float2half_rn(x0); ov.y = __float2half_rn(x1);
                *(__half2*)((__half*)out0 + off) = ov;
                if (WRELU) {
                    __half2 rw;
                    rw.x = __float2half_rn(fmaxf(x0, 0.f));
                    rw.y = __float2half_rn(fmaxf(x1, 0.f));
                    *(__half2*)(out1 + off) = rw;
                }
            }
        }
    }
}

// ================= fp8 e4m3 GEMM (decoder): m16n8k32, 3-stage, ldmatrix =================
// A: fp8 activations pre-scaled by 4096, [row][K]. B: fp8 weights [n][K].
#define QBK   128
#define QA_STR 144                       // bytes per smem row (128 + 16 pad)
#define QAS   (128 * QA_STR)             // 18432 B
#define QBS   (256 * QA_STR)             // 36864 B
#define SMEM_Q (3 * (QAS + QBS))         // 165888 B

template<int EPI, bool QRELU, bool WH16>
__global__ void __launch_bounds__(256, 1)
gemm_q(const uint8_t* __restrict__ Ain, const uint8_t* __restrict__ WT,
       const float* __restrict__ bias,
       const float* __restrict__ gamma, const float* __restrict__ beta,
       const float* __restrict__ mean,  const float* __restrict__ var,
       const __half* __restrict__ res,
       void* __restrict__ out0, uint8_t* __restrict__ out1,
       int M, int N, int K)
{
    extern __shared__ char smem[];
    const uint32_t s_a = (uint32_t)__cvta_generic_to_shared(smem);
    const uint32_t s_b = s_a + 3 * QAS;

    const int tid  = threadIdx.x;
    const int lane = tid & 31;
    const int warp = tid >> 5;
    const int wm   = warp >> 2;
    const int wn   = warp & 3;
    const int row0 = blockIdx.y * 128;
    const int col0 = blockIdx.x * 256;
    const int l4   = lane >> 2;
    const int lm   = lane & 3;
    const int t8   = lane >> 3;
    const int jr   = lane & 7;

    uint32_t aBase[4], bBase[4];
#pragma unroll
    for (int mt = 0; mt < 4; mt++) {
        int r = wm * 64 + mt * 16 + ((t8 & 1) << 3) + jr;
        int cB = (t8 >> 1) << 4;        // byte col 0 or 16
        aBase[mt] = s_a + (uint32_t)(r * QA_STR + cB);
    }
#pragma unroll
    for (int p = 0; p < 4; p++) {
        int r = wn * 64 + (2 * p + (t8 >> 1)) * 8 + jr;
        int cB = (t8 & 1) << 4;
        bBase[p] = s_b + (uint32_t)(r * QA_STR + cB);
    }

    float acc[4][8][4];
#pragma unroll
    for (int mt = 0; mt < 4; mt++)
#pragma unroll
        for (int nt = 0; nt < 8; nt++)
#pragma unroll
            for (int q = 0; q < 4; q++) acc[mt][nt][q] = 0.f;

    const int iters = K / QBK;

    auto loadA = [&](int s, int k0) {
#pragma unroll
        for (int i = 0; i < 4; i++) {
            int idx = i * 256 + tid;
            int r = idx >> 3, c16 = idx & 7;
            cp16(s_a + (uint32_t)(s * QAS) + (uint32_t)(r * QA_STR + c16 * 16),
                 Ain + (size_t)(row0 + r) * K + k0 + c16 * 16);
        }
    };
    auto loadB = [&](int s, int k0) {
#pragma unroll
        for (int i = 0; i < 8; i++) {
            int idx = i * 256 + tid;
            int n = idx >> 3, c16 = idx & 7;
            cp16(s_b + (uint32_t)(s * QBS) + (uint32_t)(n * QA_STR + c16 * 16),
                 WT + (size_t)(col0 + n) * K + k0 + c16 * 16);
        }
    };

    loadA(0, 0); loadB(0, 0); cp_commit();
    loadA(1, QBK); loadB(1, QBK); cp_commit();

    for (int it = 0; it < iters; it++) {
        if (it + 1 < iters) cp_wait<1>(); else cp_wait<0>();
        __syncthreads();
        if (it + 2 < iters) {
            int ps = (it + 2) % 3;
            loadA(ps, (it + 2) * QBK);
            loadB(ps, (it + 2) * QBK);
            cp_commit();
        }

        const int s = it % 3;
        const uint32_t aOff = (uint32_t)(s * QAS);
        const uint32_t bOff = (uint32_t)(s * QBS);
#pragma unroll
        for (int kk = 0; kk < QBK; kk += 32) {
            uint32_t af[4][4], bf[8][2];
#pragma unroll
            for (int mt = 0; mt < 4; mt++)
                ldsm4(af[mt][0], af[mt][1], af[mt][2], af[mt][3],
                      aBase[mt] + aOff + (uint32_t)kk);
#pragma unroll
            for (int p = 0; p < 4; p++)
                ldsm4(bf[2 * p][0], bf[2 * p][1], bf[2 * p + 1][0], bf[2 * p + 1][1],
                      bBase[p] + bOff + (uint32_t)kk);
#pragma unroll
            for (int mt = 0; mt < 4; mt++)
#pragma unroll
                for (int nt = 0; nt < 8; nt++)
                    mmaq(acc[mt][nt], af[mt], bf[nt]);
        }
    }

    // ---- epilogue ----
#pragma unroll
    for (int nt = 0; nt < 8; nt++) {
        int c = col0 + wn * 64 + nt * 8 + (lm << 1);
        float b0 = bias[c], b1 = bias[c + 1];
        float g0 = 0.f, g1 = 0.f, be0 = 0.f, be1 = 0.f, m0 = 0.f, m1 = 0.f;
        if (EPI == EPI_RES) {
            g0 = gamma[c]     * rsqrtf(var[c]     + 1e-5f);
            g1 = gamma[c + 1] * rsqrtf(var[c + 1] + 1e-5f);
            be0 = beta[c]; be1 = beta[c + 1];
            m0 = mean[c]; m1 = mean[c + 1];
        }
#pragma unroll
        for (int mt = 0; mt < 4; mt++) {
#pragma unroll
            for (int h = 0; h < 2; h++) {
                int r = row0 + wm * 64 + mt * 16 + l4 + h * 8;
                size_t off = (size_t)r * N + c;
                float x0 = acc[mt][nt][h * 2 + 0] * QSCALE_INV + b0;
                float x1 = acc[mt][nt][h * 2 + 1] * QSCALE_INV + b1;
                if (EPI == EPI_SIG) {
                    float* o = (float*)out0;
                    o[off]     = 1.f / (1.f + expf(-x0));
                    o[off + 1] = 1.f / (1.f + expf(-x1));
                    continue;
                }
                // EPI_RES
                __half2 rv = *(const __half2*)(res + off);
                x0 = (x0 - m0) * g0 + be0 + __half2float(rv.x);
                x1 = (x1 - m1) * g1 + be1 + __half2float(rv.y);
                if (WH16) {
                    __half2 ov; ov.x = __float2half_rn(x0); ov.y = __float2half_rn(x1);
                    *(__half2*)((__half*)out0 + off) = ov;
                }
                float q0 = QRELU ? fmaxf(x0, 0.f) * QSCALE : x0 * QSCALE;
                float q1 = QRELU ? fmaxf(x1, 0.f) * QSCALE : x1 * QSCALE;
                *(uint16_t*)(out1 + off) = pack_q2(q0, q1);
            }
        }
    }
}

// ================= VQ: fp16 mma distances + fused argmin (R8 proven) =================
#define AZ_STR 264
#define VQ_SMEM (128 * AZ_STR * 2 + 3 * HBS * 2)

__global__ void __launch_bounds__(256, 1)
vq_h(const __half* __restrict__ Z, const __half* __restrict__ CBH)
{
    extern __shared__ char smem[];
    __half* Az = (__half*)smem;
    __half* Bh = (__half*)(smem + 128 * AZ_STR * 2);
    const uint32_t s_az = (uint32_t)__cvta_generic_to_shared(Az);
    const uint32_t s_b  = (uint32_t)__cvta_generic_to_shared(Bh);
    __shared__ float sv[128][4];
    __shared__ int   si[128][4];

    const int tid  = threadIdx.x;
    const int lane = tid & 31;
    const int warp = tid >> 5;
    const int wm   = warp >> 2;
    const int wn   = warp & 3;
    const int row0 = blockIdx.x * 128;
    const int l4   = lane >> 2;
    const int lm   = lane & 3;
    const int t8   = lane >> 3;
    const int jr   = lane & 7;

    uint32_t aBase[4], bBase[4];
#pragma unroll
    for (int mt = 0; mt < 4; mt++) {
        int r = wm * 64 + mt * 16 + ((t8 & 1) << 3) + jr;
        int c = (t8 >> 1) << 3;
        aBase[mt] = s_az + (uint32_t)(r * AZ_STR + c) * 2;
    }
#pragma unroll
    for (int p = 0; p < 4; p++) {
        int r = wn * 64 + (2 * p + (t8 >> 1)) * 8 + jr;
        int c = (t8 & 1) << 3;
        bBase[p] = s_b + (uint32_t)(r * HA_STR + c) * 2;
    }

    auto loadB = [&](int s, int chunk) {
        int ct = chunk >> 2, k0 = (chunk & 3) * 64;
#pragma unroll
        for (int i = 0; i < 8; i++) {
            int idx = i * 256 + tid;
            int code = idx >> 3, kc = (idx & 7) << 3;
            cp16(s_b + (uint32_t)(s * (HBS * 2)) + (uint32_t)(code * HA_STR + kc) * 2,
                 CBH + (size_t)(ct * 256 + code) * NCD + k0 + kc);
        }
    };

#pragma unroll
    for (int i = 0; i < 16; i++) {
        int idx = i * 256 + tid;
        int r = idx >> 5, kc = (idx & 31) << 3;
        cp16(s_az + (uint32_t)(r * AZ_STR + kc) * 2,
             Z + (size_t)(row0 + r) * NCD + kc);
    }
    loadB(0, 0); cp_commit();
    loadB(1, 1); cp_commit();

    float minv[4][2];
    int   mini[4][2];
#pragma unroll
    for (int mt = 0; mt < 4; mt++)
#pragma unroll
        for (int h = 0; h < 2; h++) { minv[mt][h] = 3.4e38f; mini[mt][h] = 0; }

    float acc[4][8][4];
#pragma unroll
    for (int mt = 0; mt < 4; mt++)
#pragma unroll
        for (int nt = 0; nt < 8; nt++)
#pragma unroll
            for (int q = 0; q < 4; q++) acc[mt][nt][q] = 0.f;

    for (int c = 0; c < 64; c++) {
        if (c + 1 < 64) cp_wait<1>(); else cp_wait<0>();
        __syncthreads();
        if (c + 2 < 64) { loadB((c + 2) % 3, c + 2); cp_commit(); }

        const int s = c % 3;
        const uint32_t bOff = (uint32_t)(s * (HBS * 2));
        const int kg = (c & 3) * 64;
#pragma unroll
        for (int kk = 0; kk < 64; kk += 16) {
            uint32_t af[4][4], bf[8][2];
#pragma unroll
            for (int mt = 0; mt < 4; mt++)
                ldsm4(af[mt][0], af[mt][1], af[mt][2], af[mt][3],
                      aBase[mt] + (uint32_t)(kg + kk) * 2);
#pragma unroll
            for (int p = 0; p < 4; p++)
                ldsm4(bf[2 * p][0], bf[2 * p][1], bf[2 * p + 1][0], bf[2 * p + 1][1],
                      bBase[p] + bOff + (uint32_t)kk * 2);
#pragma unroll
            for (int mt = 0; mt < 4; mt++)
#pragma unroll
                for (int nt = 0; nt < 8; nt++)
                    mma16(acc[mt][nt], af[mt], bf[nt]);
        }

        if ((c & 3) == 3) {
            int ct = (c >> 2) * 256;
#pragma unroll
            for (int nt = 0; nt < 8; nt++) {
                int code = ct + wn * 64 + nt * 8 + (lm << 1);
                float cn0 = g_cnorm[code], cn1 = g_cnorm[code + 1];
#pragma unroll
                for (int mt = 0; mt < 4; mt++)
#pragma unroll
                    for (int h = 0; h < 2; h++) {
                        float d0 = cn0 - 2.f * acc[mt][nt][h * 2 + 0];
                        float d1 = cn1 - 2.f * acc[mt][nt][h * 2 + 1];
                        if (d0 < minv[mt][h]) { minv[mt][h] = d0; mini[mt][h] = code; }
                        if (d1 < minv[mt][h]) { minv[mt][h] = d1; mini[mt][h] = code + 1; }
                        acc[mt][nt][h * 2 + 0] = 0.f;
                        acc[mt][nt][h * 2 + 1] = 0.f;
                    }
            }
        }
    }

#pragma unroll
    for (int mt = 0; mt < 4; mt++)
#pragma unroll
        for (int h = 0; h < 2; h++) {
            float v = minv[mt][h]; int ix = mini[mt][h];
#pragma unroll
            for (int o = 1; o <= 2; o <<= 1) {
                float vo = __shfl_xor_sync(0xffffffffu, v, o);
                int   io = __shfl_xor_sync(0xffffffffu, ix, o);
                if (vo < v || (vo == v && io < ix)) { v = vo; ix = io; }
            }
            if (lm == 0) {
                int rl = wm * 64 + mt * 16 + l4 + h * 8;
                sv[rl][wn] = v; si[rl][wn] = ix;
            }
        }
    __syncthreads();
    if (tid < 128) {
        float bv = sv[tid][0]; int bi = si[tid][0];
#pragma unroll
        for (int t = 1; t < 4; t++) {
            float v = sv[tid][t]; int k2 = si[tid][t];
            if (v < bv || (v == bv && k2 < bi)) { bv = v; bi = k2; }
        }
        g_idx[row0 + tid] = bi;
        atomicAdd(&g_cnt[bi], 1);
    }
}

// ---------------- pre-pass kernels ----------------
// merged: zero counts + cb fp32->fp16 + codebook norms (one launch)
__global__ __launch_bounds__(256)
void prep_cb(const float* __restrict__ CB, __half* __restrict__ CBH)
{
    int warp = threadIdx.x >> 5, lane = threadIdx.x & 31;
    int code = blockIdx.x * 8 + warp;
    const float* c = CB + (size_t)code * NCD;
    __half* ch = CBH + (size_t)code * NCD;
    float s = 0.f;
#pragma unroll
    for (int e = 0; e < 8; e++) {
        int d = e * 32 + lane;
        __half hv = __float2half_rn(c[d]);
        ch[d] = hv;
        float v = __half2float(hv);
        s += v * v;
    }
#pragma unroll
    for (int o = 16; o > 0; o >>= 1) s += __shfl_xor_sync(0xffffffffu, s, o);
    if (lane == 0) { g_cnorm[code] = s; g_cnt[code] = 0; }
}

__global__ void transpose_f16(const float* __restrict__ W, __half* __restrict__ WT,
                              int K, int N)
{
    __shared__ float t[32][33];
    int n0 = blockIdx.x * 32, k0 = blockIdx.y * 32;
    int tx = threadIdx.x, ty = threadIdx.y;
#pragma unroll
    for (int i = 0; i < 32; i += 8)
        t[ty + i][tx] = W[(size_t)(k0 + ty + i) * N + n0 + tx];
    __syncthreads();
#pragma unroll
    for (int i = 0; i < 32; i += 8)
        WT[(size_t)(n0 + ty + i) * K + k0 + tx] = __float2half_rn(t[tx][ty + i]);
}

// z=0..2 -> fp16 (W2, rb0, rb1); z=3..5 -> fp8 (rb2, rb3, rb4)
__global__ void transpose_sq6(const float* __restrict__ W2, const float* __restrict__ rbW,
                              __half* __restrict__ dh, uint8_t* __restrict__ dq)
{
    __shared__ float t[32][33];
    int z = blockIdx.z;
    const float* src = (z == 0) ? W2 : rbW + (size_t)(z - 1) * NEMB * NEMB;
    int n0 = blockIdx.x * 32, k0 = blockIdx.y * 32;
    int tx = threadIdx.x, ty = threadIdx.y;
#pragma unroll
    for (int i = 0; i < 32; i += 8)
        t[ty + i][tx] = src[(size_t)(k0 + ty + i) * NEMB + n0 + tx];
    __syncthreads();
    if (z < 3) {
        __half* out = dh + (size_t)z * NEMB * NEMB;
#pragma unroll
        for (int i = 0; i < 32; i += 8)
            out[(size_t)(n0 + ty + i) * NEMB + k0 + tx] = __float2half_rn(t[tx][ty + i]);
    } else {
        uint8_t* out = dq + (size_t)(z - 3) * NEMB * NEMB;
#pragma unroll
        for (int i = 0; i < 32; i += 8)
            out[(size_t)(n0 + ty + i) * NEMB + k0 + tx] =
                (uint8_t)__nv_cvt_float_to_fp8(t[tx][ty + i], __NV_SATFINITE, __NV_E4M3);
    }
}

__global__ void transpose_q8(const float* __restrict__ W, uint8_t* __restrict__ WT,
                             int K, int N)
{
    __shared__ float t[32][33];
    int n0 = blockIdx.x * 32, k0 = blockIdx.y * 32;
    int tx = threadIdx.x, ty = threadIdx.y;
#pragma unroll
    for (int i = 0; i < 32; i += 8)
        t[ty + i][tx] = W[(size_t)(k0 + ty + i) * N + n0 + tx];
    __syncthreads();
#pragma unroll
    for (int i = 0; i < 32; i += 8)
        WT[(size_t)(n0 + ty + i) * K + k0 + tx] =
            (uint8_t)__nv_cvt_float_to_fp8(t[tx][ty + i], __NV_SATFINITE, __NV_E4M3);
}

// gather quantized (fp16 hq for residual + fp8 relu(hq)*S for decoder MMA) + loss partials
__global__ __launch_bounds__(256)
void gather_loss_kernel(const __half* __restrict__ Z, const float* __restrict__ CB,
                        __half* __restrict__ HQ, uint8_t* __restrict__ Q)
{
    __shared__ float ws[8];
    int warp = threadIdx.x >> 5, lane = threadIdx.x & 31;
    int row  = blockIdx.x * 8 + warp;
    int id   = g_idx[row];
    const float*  q = CB + (size_t)id * NCD;
    const __half* z = Z + (size_t)row * NCD;
    __half*  o  = HQ + (size_t)row * NCD;
    uint8_t* oq = Q  + (size_t)row * NCD;
    float s = 0.f;
#pragma unroll
    for (int e = 0; e < 8; e++) {
        int d = e * 32 + lane;
        float qq = q[d], zz = __half2float(z[d]);
        o[d]  = __float2half_rn(qq);
        oq[d] = (uint8_t)__nv_cvt_float_to_fp8(fmaxf(qq, 0.f) * QSCALE,
                                               __NV_SATFINITE, __NV_E4M3);
        float t = qq - zz;
        s += t * t;
    }
#pragma unroll
    for (int off = 16; off > 0; off >>= 1) s += __shfl_xor_sync(0xffffffffu, s, off);
    if (lane == 0) ws[warp] = s;
    __syncthreads();
    if (threadIdx.x == 0) {
        float t = 0.f;
#pragma unroll
        for (int w = 0; w < 8; w++) t += ws[w];
        g_losspart[blockIdx.x] = t;
    }
}

__global__ __launch_bounds__(256)
void finalize_kernel(float* __restrict__ out)
{
    __shared__ float red[256];
    int tid = threadIdx.x;

    float s = 0.f;
    for (int i = tid; i < NFLAT / 8; i += 256) s += g_losspart[i];
    red[tid] = s; __syncthreads();
    for (int o = 128; o > 0; o >>= 1) { if (tid < o) red[tid] += red[tid + o]; __syncthreads(); }
    float loss = red[0] * (1.25f / ((float)NB * (float)NEMB));
    __syncthreads();

    float e = 0.f;
    for (int i = tid; i < NK; i += 256) {
        float p = (float)g_cnt[i] * (1.0f / (float)NFLAT);
        e += p * logf(p + 1e-10f);
    }
    red[tid] = e; __syncthreads();
    for (int o = 128; o > 0; o >>= 1) { if (tid < o) red[tid] += red[tid + o]; __syncthreads(); }

    if (tid == 0) {
        out[0]            = loss;
        out[OUT_PERP_OFF] = expf(-red[0]);
    }
}

// ---------------- launch ----------------
extern "C" void kernel_launch(void* const* d_in, const int* in_sizes, int n_in,
                              void* d_out, int out_size)
{
    const float* x    = (const float*)d_in[0];
    const float* W1   = (const float*)d_in[1];
    const float* b1   = (const float*)d_in[2];
    const float* bn1g = (const float*)d_in[3];
    const float* bn1b = (const float*)d_in[4];
    const float* bn1m = (const float*)d_in[5];
    const float* bn1v = (const float*)d_in[6];
    const float* W2   = (const float*)d_in[7];
    const float* b2   = (const float*)d_in[8];
    const float* rbW  = (const float*)d_in[9];
    const float* rbb  = (const float*)d_in[10];
    const float* rbg  = (const float*)d_in[11];
    const float* rbbe = (const float*)d_in[12];
    const float* rbm  = (const float*)d_in[13];
    const float* rbv  = (const float*)d_in[14];
    const float* cb   = (const float*)d_in[15];
    const float* decW = (const float*)d_in[16];
    const float* decb = (const float*)d_in[17];
    float* out = (float*)d_out;

    __half *w1t, *wts, *cbh, *ha, *har, *hb, *hbr, *gz;
    uint8_t *wq, *wqd, *q1, *q2;
    cudaGetSymbolAddress((void**)&w1t, g_w1t);
    cudaGetSymbolAddress((void**)&wts, g_wts);
    cudaGetSymbolAddress((void**)&wq,  g_wq);
    cudaGetSymbolAddress((void**)&wqd, g_wqd);
    cudaGetSymbolAddress((void**)&cbh, g_cbh);
    cudaGetSymbolAddress((void**)&ha,  g_ha);
    cudaGetSymbolAddress((void**)&har, g_har);
    cudaGetSymbolAddress((void**)&hb,  g_hb);
    cudaGetSymbolAddress((void**)&hbr, g_hbr);
    cudaGetSymbolAddress((void**)&gz,  g_z);
    cudaGetSymbolAddress((void**)&q1,  g_q1);
    cudaGetSymbolAddress((void**)&q2,  g_q2);

    cudaFuncSetAttribute(gemm_h<EPI_BN_RELU, false, true >, cudaFuncAttributeMaxDynamicSharedMemorySize, SMEM_H32);
    cudaFuncSetAttribute(gemm_h<EPI_BIAS,    true,  false>, cudaFuncAttributeMaxDynamicSharedMemorySize, SMEM_H16);
    cudaFuncSetAttribute(gemm_h<EPI_RES,     true,  false>, cudaFuncAttributeMaxDynamicSharedMemorySize, SMEM_H16);
    cudaFuncSetAttribute(gemm_h<EPI_RES,     false, false>, cudaFuncAttributeMaxDynamicSharedMemorySize, SMEM_H16);
    cudaFuncSetAttribute(gemm_q<EPI_RES,  true,  true >, cudaFuncAttributeMaxDynamicSharedMemorySize, SMEM_Q);
    cudaFuncSetAttribute(gemm_q<EPI_RES,  false, false>, cudaFuncAttributeMaxDynamicSharedMemorySize, SMEM_Q);
    cudaFuncSetAttribute(gemm_q<EPI_SIG,  false, false>, cudaFuncAttributeMaxDynamicSharedMemorySize, SMEM_Q);
    cudaFuncSetAttribute(vq_h, cudaFuncAttributeMaxDynamicSharedMemorySize, VQ_SMEM);

    const size_t WS = (size_t)NEMB * NEMB;
    dim3 tb(32, 8);
    dim3 blk(256);
    dim3 gE(NEMB / 256, NB / 128);   // 4 x 32
    dim3 gD(NIN / 256,  NB / 128);   // 32 x 32

    // pre-pass (4 launches)
    prep_cb<<<NK / 8, 256>>>(cb, cbh);
    transpose_f16<<<dim3(NEMB / 32, NIN / 32),  tb>>>(W1, w1t, NIN, NEMB);
    transpose_sq6<<<dim3(32, 32, 6), tb>>>(W2, rbW, wts, wq);
    transpose_q8<<<dim3(NIN / 32, NEMB / 32), tb>>>(decW, wqd, NEMB, NIN);

    __half* w2t = wts + 0 * WS;
    __half* wt0 = wts + 1 * WS;
    __half* wt1 = wts + 2 * WS;

    // encoder (fp16 mma; enc1 reads fp32 x, packs at fragment load)
    gemm_h<EPI_BN_RELU, false, true><<<gE, blk, SMEM_H32>>>(
        x, w1t, b1, bn1g, bn1b, bn1m, bn1v, nullptr, har, nullptr, NB, NEMB, NIN);
    gemm_h<EPI_BIAS, true, false><<<gE, blk, SMEM_H16>>>(
        har, w2t, b2, nullptr, nullptr, nullptr, nullptr, nullptr, hb, hbr, NB, NEMB, NEMB);
    gemm_h<EPI_RES, true, false><<<gE, blk, SMEM_H16>>>(
        hbr, wt0, rbb + 0 * NEMB, rbg + 0 * NEMB, rbbe + 0 * NEMB,
        rbm + 0 * NEMB, rbv + 0 * NEMB, hb, ha, har, NB, NEMB, NEMB);
    gemm_h<EPI_RES, false, false><<<gE, blk, SMEM_H16>>>(
        har, wt1, rbb + 1 * NEMB, rbg + 1 * NEMB, rbbe + 1 * NEMB,
        rbm + 1 * NEMB, rbv + 1 * NEMB, ha, gz, nullptr, NB, NEMB, NEMB);

    // vector quantizer
    vq_h<<<NFLAT / 128, blk, VQ_SMEM>>>(gz, cbh);
    gather_loss_kernel<<<NFLAT / 8, 256>>>(gz, cb, hb, q1);
    finalize_kernel<<<1, 256>>>(out);

    // decoder (fp8 e4m3 mma, activations scaled by 4096)
    gemm_q<EPI_RES, true, true><<<gE, blk, SMEM_Q>>>(
        q1, wq + 0 * WS, rbb + 2 * NEMB, rbg + 2 * NEMB, rbbe + 2 * NEMB,
        rbm + 2 * NEMB, rbv + 2 * NEMB, hb, ha, q2, NB, NEMB, NEMB);
    gemm_q<EPI_RES, true, true><<<gE, blk, SMEM_Q>>>(
        q2, wq + 1 * WS, rbb + 3 * NEMB, rbg + 3 * NEMB, rbbe + 3 * NEMB,
        rbm + 3 * NEMB, rbv + 3 * NEMB, ha, hb, q1, NB, NEMB, NEMB);
    gemm_q<EPI_RES, false, false><<<gE, blk, SMEM_Q>>>(
        q1, wq + 2 * WS, rbb + 4 * NEMB, rbg + 4 * NEMB, rbbe + 4 * NEMB,
        rbm + 4 * NEMB, rbv + 4 * NEMB, hb, nullptr, q2, NB, NEMB, NEMB);
    gemm_q<EPI_SIG, false, false><<<gD, blk, SMEM_Q>>>(
        q2, wqd, decb, nullptr, nullptr, nullptr, nullptr, nullptr,
        out + 1, nullptr, NB, NIN, NEMB);
}